// round 10
// baseline (speedup 1.0000x reference)
#include <cuda_runtime.h>
#include <cuda_fp16.h>
#include <cstdint>
#include <cstddef>

#define N_NODES 20000
#define N_EDGES 160000
#define MUL0 32
#define MUL1 16
#define NODE_DIM 80
#define EDGE_FEAT 128
#define HIDDEN 128
#define W_NUMEL 2560
#define MTILE 256
#define NTILES (N_EDGES / MTILE)      // 625
#define NCHUNK 64
#define NCHUNKS (W_NUMEL / NCHUNK)    // 40

#define C0f   0.14433756729740643f
#define C1f   0.21650635094610965f
#define IS3f  0.5773502691896258f
#define IS6f  0.40824829046386296f
#define C0IS3 (C0f * IS3f)
#define C1IS3 (C1f * IS3f)
#define C1IS6 (C1f * IS6f)
#define EPS_LN 1e-5f

// ---------------- device scratch ----------------
__device__ __align__(16) __half g_A[(size_t)N_EDGES * HIDDEN];     // h fp16, [e][k]
__device__ __align__(16) __half g_Bf16[(size_t)W_NUMEL * HIDDEN];  // W2^T fp16 [n][k]
__device__ float g_seg[(size_t)N_NODES * NODE_DIM];
__device__ float g_cnt[N_NODES];

// ---------------- PTX helpers ----------------
__device__ __forceinline__ uint32_t smem_u32(const void* p) {
    uint32_t a;
    asm("{ .reg .u64 t; cvta.to.shared.u64 t, %1; cvt.u32.u64 %0, t; }" : "=r"(a) : "l"(p));
    return a;
}
__device__ __forceinline__ void ldsm_x4(uint32_t* r, uint32_t addr) {
    asm volatile("ldmatrix.sync.aligned.m8n8.x4.shared.b16 {%0,%1,%2,%3}, [%4];"
        : "=r"(r[0]), "=r"(r[1]), "=r"(r[2]), "=r"(r[3]) : "r"(addr));
}
__device__ __forceinline__ void mma_f16(float* c, const uint32_t* a, uint32_t b0, uint32_t b1) {
    asm volatile("mma.sync.aligned.m16n8k16.row.col.f32.f16.f16.f32 "
        "{%0,%1,%2,%3}, {%4,%5,%6,%7}, {%8,%9}, {%0,%1,%2,%3};"
        : "+f"(c[0]), "+f"(c[1]), "+f"(c[2]), "+f"(c[3])
        : "r"(a[0]), "r"(a[1]), "r"(a[2]), "r"(a[3]), "r"(b0), "r"(b1));
}
__device__ __forceinline__ void cp_async16(uint32_t smem_addr, const void* gptr) {
    asm volatile("cp.async.ca.shared.global [%0], [%1], 16;" :: "r"(smem_addr), "l"(gptr));
}
#define CP_COMMIT() asm volatile("cp.async.commit_group;" ::: "memory")
#define CP_WAIT_0() asm volatile("cp.async.wait_group 0;" ::: "memory")
#define CP_WAIT_1() asm volatile("cp.async.wait_group 1;" ::: "memory")

#define ROWB 272

// ---------------- GEMM1 (fp16 2-pass A hi/lo) + embedded prep (unchanged champion) ----------------
#define G1_AHI 0
#define G1_ALO 34816
#define G1_W   69632
#define G1_B1  104448
#define G1_SMEM 104960

__global__ __launch_bounds__(256, 2)
void gemm1_kernel(const float* __restrict__ edge_attr,
                  const float* __restrict__ fc_w1,
                  const float* __restrict__ fc_b1,
                  const float* __restrict__ fc_w2) {
    extern __shared__ char smc[];
    const uint32_t smb = smem_u32(smc);
    const int tid = threadIdx.x;
    const int w = tid >> 5;
    const int lane = tid & 31;
    const int e0 = blockIdx.x * 128;

    // embedded prep (block-strided)
    {
        const int gt = blockIdx.x * 256 + tid;
        const int gs = gridDim.x * 256;
        for (int i = gt; i < N_NODES * NODE_DIM; i += gs) g_seg[i] = 0.0f;
        for (int i = gt; i < N_NODES; i += gs) g_cnt[i] = 0.0f;
        for (int i = gt; i < HIDDEN * W_NUMEL; i += gs) {
            const int n = i >> 7, k = i & 127;
            g_Bf16[i] = __float2half_rn(fc_w2[(size_t)k * W_NUMEL + n]);
        }
    }

    // W1 fp32 -> fp16 transposed into SMEM
    for (int i = tid; i < HIDDEN * HIDDEN; i += 256) {
        const int k = i >> 7, n = i & 127;
        *(__half*)(smc + G1_W + n * ROWB + k * 2) = __float2half_rn(fc_w1[i]);
    }

    // stage A: fp32 -> fp16 hi/lo
    const float4* ga = (const float4*)(edge_attr + (size_t)e0 * EDGE_FEAT);
#pragma unroll
    for (int it = 0; it < 16; it++) {
        const int i = tid + it * 256;
        const int row = i >> 5, kc4 = i & 31;
        const float4 v = ga[i];
        const __half hx = __float2half_rn(v.x), hy = __float2half_rn(v.y);
        const __half hz = __float2half_rn(v.z), hw = __float2half_rn(v.w);
        const __half lx = __float2half_rn(v.x - __half2float(hx));
        const __half ly = __float2half_rn(v.y - __half2float(hy));
        const __half lz = __float2half_rn(v.z - __half2float(hz));
        const __half lw = __float2half_rn(v.w - __half2float(hw));
        char* dh = smc + G1_AHI + row * ROWB + kc4 * 8;
        char* dl = smc + G1_ALO + row * ROWB + kc4 * 8;
        *(__half2*)(dh)     = __halves2half2(hx, hy);
        *(__half2*)(dh + 4) = __halves2half2(hz, hw);
        *(__half2*)(dl)     = __halves2half2(lx, ly);
        *(__half2*)(dl + 4) = __halves2half2(lz, lw);
    }
    if (tid < 128) ((float*)(smc + G1_B1))[tid] = fc_b1[tid];
    __syncthreads();

    const int q2 = 2 * (lane & 3);
    const int r8 = lane >> 2;
    const int mA = 16 * w + r8;

    const uint32_t aRow = (uint32_t)(16 * w + (lane & 7) + ((lane >> 3) & 1) * 8);
    const uint32_t aK = (uint32_t)(((lane >> 4) & 1) * 16);
    const uint32_t aHiB = smb + G1_AHI + aRow * ROWB + aK;
    const uint32_t aLoB = smb + G1_ALO + aRow * ROWB + aK;
    const uint32_t bRow = (uint32_t)((lane & 7) + ((lane >> 4) & 1) * 8);
    const uint32_t bK = (uint32_t)(((lane >> 3) & 1) * 16);
    const uint32_t wB = smb + G1_W + bRow * ROWB + bK;

    float c[16][4];
#pragma unroll
    for (int t = 0; t < 16; t++)
#pragma unroll
        for (int i = 0; i < 4; i++) c[t][i] = 0.0f;

#pragma unroll
    for (int ks = 0; ks < 8; ks++) {
        uint32_t ah[4], al[4];
        ldsm_x4(ah, aHiB + ks * 32);
        ldsm_x4(al, aLoB + ks * 32);
#pragma unroll
        for (int tp = 0; tp < 8; tp++) {
            uint32_t wf[4];
            ldsm_x4(wf, wB + tp * (16 * ROWB) + ks * 32);
            mma_f16(c[2 * tp],     ah, wf[0], wf[1]);
            mma_f16(c[2 * tp],     al, wf[0], wf[1]);
            mma_f16(c[2 * tp + 1], ah, wf[2], wf[3]);
            mma_f16(c[2 * tp + 1], al, wf[2], wf[3]);
        }
    }

    const float* b1s = (const float*)(smc + G1_B1);
#pragma unroll
    for (int t = 0; t < 16; t++) {
        const int col = 8 * t + q2;
        const float bb0 = b1s[col], bb1 = b1s[col + 1];
#pragma unroll
        for (int rr = 0; rr < 2; rr++) {
            const int mm = mA + 8 * rr;
            const float v0 = fmaxf(c[t][2 * rr + 0] + bb0, 0.0f);
            const float v1 = fmaxf(c[t][2 * rr + 1] + bb1, 0.0f);
            *(__half2*)(g_A + (size_t)(e0 + mm) * HIDDEN + col) =
                __halves2half2(__float2half_rn(v0), __float2half_rn(v1));
        }
    }
}

// ---------------- edge kernel: MTILE=256, 1 CTA/SM, 3-stage B ring ----------------
// smem: A[256][272]@0 (69632), B 3x[64][272]@69632 (52224), b2s@121856 (10240),
//       x0s@132096 (33792), x1s@165888 (50176), shs@216064 (4096), srcs@220160 (1024)
#define E_A    0
#define E_B    69632
#define EBBUF  17408
#define E_B2   121856
#define E_X0   132096
#define E_X1   165888
#define E_SH   216064
#define E_SRC  220160
#define EDGE_SMEM 221184

// top of chunk j: ensure B_j landed, barrier, prefetch B_{j+2}
#define CHUNK_TOP(j) \
    if ((j) + 1 < NCHUNKS) { CP_WAIT_1(); } else { CP_WAIT_0(); } \
    __syncthreads(); \
    if ((j) + 2 < NCHUNKS) { \
        const uint32_t sb = smb + E_B + (uint32_t)((((j) + 2) % 3) * EBBUF); \
        const __half* gp0 = g_Bf16 + (size_t)((j) + 2) * NCHUNK * HIDDEN; \
        _Pragma("unroll") \
        for (int it = 0; it < 4; it++) { \
            const int i = tid + it * 256; \
            const int row = i >> 4, kc = i & 15; \
            cp_async16(sb + row * ROWB + kc * 16, gp0 + (size_t)row * HIDDEN + kc * 8); \
        } \
        CP_COMMIT(); \
    }

// 32 rows x 64 cols MMA for chunk j; issue all 128 mma before any c read
#define CHUNK_MMA(j) \
    float c2[2][8][4]; \
    { \
        _Pragma("unroll") for (int rt = 0; rt < 2; rt++) \
        _Pragma("unroll") for (int t = 0; t < 8; t++) \
        _Pragma("unroll") for (int i = 0; i < 4; i++) c2[rt][t][i] = 0.0f; \
        const uint32_t bb = smb + E_B + (uint32_t)(((j) % 3) * EBBUF) + bRowOff; \
        _Pragma("unroll") for (int ks = 0; ks < 8; ks++) { \
            uint32_t a0[4], a1[4]; \
            ldsm_x4(a0, aB0 + ks * 32); \
            ldsm_x4(a1, aB1 + ks * 32); \
            _Pragma("unroll") for (int tp = 0; tp < 4; tp++) { \
                uint32_t bf[4]; \
                ldsm_x4(bf, bb + tp * (16 * ROWB) + ks * 32); \
                mma_f16(c2[0][2 * tp],     a0, bf[0], bf[1]); \
                mma_f16(c2[0][2 * tp + 1], a0, bf[2], bf[3]); \
                mma_f16(c2[1][2 * tp],     a1, bf[0], bf[1]); \
                mma_f16(c2[1][2 * tp + 1], a1, bf[2], bf[3]); \
            } \
        } \
    }

__global__ __launch_bounds__(256, 1)
void edge_kernel(const float* __restrict__ node_attr,
                 const float* __restrict__ edge_sh,
                 const float* __restrict__ fc_b2,
                 const int*   __restrict__ edge_index) {
    extern __shared__ char smc[];
    const uint32_t smb = smem_u32(smc);
    float* b2s = (float*)(smc + E_B2);
    float* x0s = (float*)(smc + E_X0);
    float* x1s = (float*)(smc + E_X1);
    float* shs = (float*)(smc + E_SH);
    int*  srcs = (int*)(smc + E_SRC);

    const int tid  = threadIdx.x;
    const int w    = tid >> 5;          // warp -> rows 32w..32w+31
    const int lane = tid & 31;
    const int e0 = blockIdx.x * MTILE;

    // prologue cp.async: B0 + A -> group 0; B1 -> group 1
#pragma unroll
    for (int it = 0; it < 4; it++) {
        const int i = tid + it * 256;       // 0..1023 = row(64) x kc(16)
        const int row = i >> 4, kc = i & 15;
        cp_async16(smb + E_B + row * ROWB + kc * 16,
                   g_Bf16 + (size_t)row * HIDDEN + kc * 8);
    }
#pragma unroll
    for (int it = 0; it < 16; it++) {
        const int i = tid + it * 256;       // 0..4095 = row(256) x kc(16)
        const int row = i >> 4, kc = i & 15;
        cp_async16(smb + E_A + row * ROWB + kc * 16,
                   g_A + (size_t)(e0 + row) * HIDDEN + kc * 8);
    }
    CP_COMMIT();
#pragma unroll
    for (int it = 0; it < 4; it++) {        // B chunk 1 -> stage 1
        const int i = tid + it * 256;
        const int row = i >> 4, kc = i & 15;
        cp_async16(smb + E_B + EBBUF + row * ROWB + kc * 16,
                   g_Bf16 + (size_t)(NCHUNK + row) * HIDDEN + kc * 8);
    }
    CP_COMMIT();

    // b2 -> SMEM (once)
    for (int i = tid; i < W_NUMEL / 4; i += 256)
        ((float4*)b2s)[i] = ((const float4*)fc_b2)[i];

    // gather per-edge vectors (one thread per edge)
    {
        const int eg  = e0 + tid;
        const int src = edge_index[eg];
        const int dst = edge_index[N_EDGES + eg];
        srcs[tid] = src;
        atomicAdd(&g_cnt[src], 1.0f);
        const float4* na = (const float4*)(node_attr + (size_t)dst * NODE_DIM);
#pragma unroll
        for (int q = 0; q < 8; q++) {
            const float4 v = na[q];
            x0s[tid * 33 + 4 * q + 0] = v.x;
            x0s[tid * 33 + 4 * q + 1] = v.y;
            x0s[tid * 33 + 4 * q + 2] = v.z;
            x0s[tid * 33 + 4 * q + 3] = v.w;
        }
#pragma unroll
        for (int q = 0; q < 12; q++) {
            const float4 v = na[8 + q];
            x1s[tid * 49 + 4 * q + 0] = v.x;
            x1s[tid * 49 + 4 * q + 1] = v.y;
            x1s[tid * 49 + 4 * q + 2] = v.z;
            x1s[tid * 49 + 4 * q + 3] = v.w;
        }
        const float4 sh4 = *(const float4*)(edge_sh + (size_t)eg * 4);
        shs[tid * 4 + 0] = sh4.x;
        shs[tid * 4 + 1] = sh4.y;
        shs[tid * 4 + 2] = sh4.z;
        shs[tid * 4 + 3] = sh4.w;
    }

    const int q2 = 2 * (lane & 3);
    const int r8 = lane >> 2;
    // thread rows: r = 2*rt + rr -> 32w + 16rt + 8rr + r8
    int mmr[4];
#pragma unroll
    for (int r = 0; r < 4; r++) mmr[r] = 32 * w + 16 * (r >> 1) + 8 * (r & 1) + r8;

    const uint32_t aRowLoc = (uint32_t)((lane & 7) + 8 * ((lane >> 3) & 1));
    const uint32_t aK = (uint32_t)(16 * ((lane >> 4) & 1));
    const uint32_t aB0 = smb + E_A + ((uint32_t)(32 * w) + aRowLoc) * ROWB + aK;
    const uint32_t aB1 = aB0 + 16 * ROWB;
    const uint32_t bRowOff = (uint32_t)((lane & 7) + 8 * ((lane >> 4) & 1)) * ROWB
                           + (uint32_t)(16 * ((lane >> 3) & 1));

    float sh0r[4], sh1r[4][3];
    bool shLoaded = false;
#define LOAD_SH() \
    if (!shLoaded) { \
        _Pragma("unroll") for (int r = 0; r < 4; r++) { \
            sh0r[r] = shs[mmr[r] * 4 + 0]; \
            sh1r[r][0] = shs[mmr[r] * 4 + 1]; \
            sh1r[r][1] = shs[mmr[r] * 4 + 2]; \
            sh1r[r][2] = shs[mmr[r] * 4 + 3]; \
        } \
        shLoaded = true; \
    }

    // ============ phase 1: j 0..23, block1/block2 -> accO ============
    {
        float accO[4][8];
#pragma unroll
        for (int r = 0; r < 4; r++)
#pragma unroll
            for (int i = 0; i < 8; i++) accO[r][i] = 0.0f;

        for (int j = 0; j < 24; j++) {
            CHUNK_TOP(j);
            LOAD_SH();
            CHUNK_MMA(j);
#pragma unroll
            for (int gi = 0; gi < 2; gi++) {
                const int g = 2 * j + gi;
                float s[4];
                if (g < 32) {
#pragma unroll
                    for (int r = 0; r < 4; r++)
                        s[r] = C0f * sh0r[r] * x0s[mmr[r] * 33 + g];
                } else {
                    const int u = g - 32;
#pragma unroll
                    for (int r = 0; r < 4; r++)
                        s[r] = C0IS3 * (x1s[mmr[r] * 49 + 3 * u]     * sh1r[r][0]
                                      + x1s[mmr[r] * 49 + 3 * u + 1] * sh1r[r][1]
                                      + x1s[mmr[r] * 49 + 3 * u + 2] * sh1r[r][2]);
                }
#pragma unroll
                for (int tt = 0; tt < 4; tt++) {
                    const float b0 = b2s[32 * g + 8 * tt + q2];
                    const float b1 = b2s[32 * g + 8 * tt + q2 + 1];
#pragma unroll
                    for (int rt = 0; rt < 2; rt++)
#pragma unroll
                        for (int rr = 0; rr < 2; rr++) {
                            const int r = 2 * rt + rr;
                            float* cc = c2[rt][4 * gi + tt];
                            accO[r][2 * tt]     += s[r] * (cc[2 * rr]     + b0);
                            accO[r][2 * tt + 1] += s[r] * (cc[2 * rr + 1] + b1);
                        }
                }
            }
        }
        // scatter out0
#pragma unroll
        for (int r = 0; r < 4; r++) {
            float* segp = g_seg + (size_t)srcs[mmr[r]] * NODE_DIM;
#pragma unroll
            for (int tt = 0; tt < 4; tt++)
#pragma unroll
                for (int b = 0; b < 2; b++)
                    atomicAdd(segp + 8 * tt + q2 + b, accO[r][2 * tt + b]);
        }
    }

    // ============ phase 2: j 24..31, block3 -> t3 ============
    {
        float accT3[4][4];
#pragma unroll
        for (int r = 0; r < 4; r++)
#pragma unroll
            for (int i = 0; i < 4; i++) accT3[r][i] = 0.0f;

        for (int j = 24; j < 32; j++) {
            CHUNK_TOP(j);
            CHUNK_MMA(j);
#pragma unroll
            for (int gi = 0; gi < 2; gi++) {
                const int g = 2 * j + gi;
                const int u0 = 2 * (g - 48);
                float s[4][2];
#pragma unroll
                for (int r = 0; r < 4; r++) {
                    s[r][0] = C1IS3 * x0s[mmr[r] * 33 + u0];
                    s[r][1] = C1IS3 * x0s[mmr[r] * 33 + u0 + 1];
                }
#pragma unroll
                for (int tt = 0; tt < 4; tt++) {
                    const int us = tt >> 1;
                    const int sl = 2 * (tt & 1);
                    const float b0 = b2s[32 * g + 8 * tt + q2];
                    const float b1 = b2s[32 * g + 8 * tt + q2 + 1];
#pragma unroll
                    for (int rt = 0; rt < 2; rt++)
#pragma unroll
                        for (int rr = 0; rr < 2; rr++) {
                            const int r = 2 * rt + rr;
                            float* cc = c2[rt][4 * gi + tt];
                            accT3[r][sl]     += s[r][us] * (cc[2 * rr]     + b0);
                            accT3[r][sl + 1] += s[r][us] * (cc[2 * rr + 1] + b1);
                        }
                }
            }
        }
        // scatter sh1 * t3
#pragma unroll
        for (int r = 0; r < 4; r++) {
            float* segp = g_seg + (size_t)srcs[mmr[r]] * NODE_DIM;
#pragma unroll
            for (int ws = 0; ws < 2; ws++)
#pragma unroll
                for (int b = 0; b < 2; b++) {
                    const int wc = 8 * ws + q2 + b;
                    const float t3 = accT3[r][2 * ws + b];
                    atomicAdd(segp + 32 + 3 * wc + 0, sh1r[r][0] * t3);
                    atomicAdd(segp + 32 + 3 * wc + 1, sh1r[r][1] * t3);
                    atomicAdd(segp + 32 + 3 * wc + 2, sh1r[r][2] * t3);
                }
        }
    }

    // ============ phase 3: j 32..39, block4/5 -> V ============
    {
        float accV[4][4][3];
#pragma unroll
        for (int r = 0; r < 4; r++)
#pragma unroll
            for (int i = 0; i < 4; i++)
#pragma unroll
                for (int k = 0; k < 3; k++) accV[r][i][k] = 0.0f;

        for (int j = 32; j < 40; j++) {
            CHUNK_TOP(j);
            CHUNK_MMA(j);
#pragma unroll
            for (int gi = 0; gi < 2; gi++) {
                const int g = 2 * j + gi;
                const bool is5 = (g >= 72);
                const int u0 = is5 ? 2 * (g - 72) : 2 * (g - 64);
                float av[4][2][3];
#pragma unroll
                for (int r = 0; r < 4; r++) {
#pragma unroll
                    for (int us = 0; us < 2; us++) {
                        const int u = u0 + us;
                        const float xx = x1s[mmr[r] * 49 + 3 * u + 0];
                        const float xy = x1s[mmr[r] * 49 + 3 * u + 1];
                        const float xz = x1s[mmr[r] * 49 + 3 * u + 2];
                        if (!is5) {
                            const float kb = C1IS3 * sh0r[r];
                            av[r][us][0] = kb * xx;
                            av[r][us][1] = kb * xy;
                            av[r][us][2] = kb * xz;
                        } else {
                            av[r][us][0] = C1IS6 * (xy * sh1r[r][2] - xz * sh1r[r][1]);
                            av[r][us][1] = C1IS6 * (xz * sh1r[r][0] - xx * sh1r[r][2]);
                            av[r][us][2] = C1IS6 * (xx * sh1r[r][1] - xy * sh1r[r][0]);
                        }
                    }
                }
#pragma unroll
                for (int tt = 0; tt < 4; tt++) {
                    const int us = tt >> 1;
                    const int sl = 2 * (tt & 1);
                    const float b0 = b2s[32 * g + 8 * tt + q2];
                    const float b1 = b2s[32 * g + 8 * tt + q2 + 1];
#pragma unroll
                    for (int rt = 0; rt < 2; rt++)
#pragma unroll
                        for (int rr = 0; rr < 2; rr++) {
                            const int r = 2 * rt + rr;
                            float* cc = c2[rt][4 * gi + tt];
                            const float D0 = cc[2 * rr] + b0;
                            const float D1 = cc[2 * rr + 1] + b1;
#pragma unroll
                            for (int k = 0; k < 3; k++) {
                                accV[r][sl][k]     += av[r][us][k] * D0;
                                accV[r][sl + 1][k] += av[r][us][k] * D1;
                            }
                        }
                }
            }
        }
        // scatter V
#pragma unroll
        for (int r = 0; r < 4; r++) {
            float* segp = g_seg + (size_t)srcs[mmr[r]] * NODE_DIM;
#pragma unroll
            for (int ws = 0; ws < 2; ws++)
#pragma unroll
                for (int b = 0; b < 2; b++) {
                    const int wc = 8 * ws + q2 + b;
#pragma unroll
                    for (int k = 0; k < 3; k++)
                        atomicAdd(segp + 32 + 3 * wc + k, accV[r][2 * ws + b][k]);
                }
        }
    }
}

// ---------------- node epilogue ----------------
__global__ void node_kernel(const float* __restrict__ node_attr,
                            const float* __restrict__ mean_shift,
                            const float* __restrict__ aw,
                            const float* __restrict__ ab,
                            float* __restrict__ out) {
    const int warp = (blockIdx.x * blockDim.x + threadIdx.x) >> 5;
    const int lane = threadIdx.x & 31;
    if (warp >= N_NODES) return;
    const unsigned full = 0xFFFFFFFFu;

    const float inv = 1.0f / fmaxf(g_cnt[warp], 1.0f);
    const float* seg = g_seg + (size_t)warp * NODE_DIM;
    const float* na  = node_attr + (size_t)warp * NODE_DIM;

    float o0 = seg[lane] * inv + na[lane];
    float mval = o0;
#pragma unroll
    for (int off = 16; off; off >>= 1) mval += __shfl_xor_sync(full, mval, off);
    mval *= (1.0f / 32.0f);
    const float f0 = o0 - mval * mean_shift[lane];
    float s = f0 * f0;
#pragma unroll
    for (int off = 16; off; off >>= 1) s += __shfl_xor_sync(full, s, off);
    const float sc0 = rsqrtf(s * (1.0f / 32.0f) + EPS_LN) * aw[lane];
    out[(size_t)warp * NODE_DIM + lane] = f0 * sc0 + ab[lane];

    float vx = 0.0f, vy = 0.0f, vz = 0.0f, msv = 0.0f;
    if (lane < 16) {
        vx = seg[32 + 3 * lane + 0] * inv + na[32 + 3 * lane + 0];
        vy = seg[32 + 3 * lane + 1] * inv + na[32 + 3 * lane + 1];
        vz = seg[32 + 3 * lane + 2] * inv + na[32 + 3 * lane + 2];
        msv = mean_shift[32 + lane];
    }
    float mx = vx, my = vy, mz = vz;
#pragma unroll
    for (int off = 16; off; off >>= 1) {
        mx += __shfl_xor_sync(full, mx, off);
        my += __shfl_xor_sync(full, my, off);
        mz += __shfl_xor_sync(full, mz, off);
    }
    mx *= (1.0f / 16.0f); my *= (1.0f / 16.0f); mz *= (1.0f / 16.0f);
    const float fx = vx - mx * msv;
    const float fy = vy - my * msv;
    const float fz = vz - mz * msv;
    float sq = (lane < 16) ? (fx * fx + fy * fy + fz * fz) : 0.0f;
#pragma unroll
    for (int off = 16; off; off >>= 1) sq += __shfl_xor_sync(full, sq, off);
    if (lane < 16) {
        const float sc1 = rsqrtf(sq * (1.0f / 48.0f) + EPS_LN) * aw[32 + lane];
        out[(size_t)warp * NODE_DIM + 32 + 3 * lane + 0] = fx * sc1;
        out[(size_t)warp * NODE_DIM + 32 + 3 * lane + 1] = fy * sc1;
        out[(size_t)warp * NODE_DIM + 32 + 3 * lane + 2] = fz * sc1;
    }
}

// ---------------- launch ----------------
extern "C" void kernel_launch(void* const* d_in, const int* in_sizes, int n_in,
                              void* d_out, int out_size) {
    const float* node_attr  = (const float*)d_in[0];
    const float* edge_attr  = (const float*)d_in[1];
    const float* edge_sh    = (const float*)d_in[2];
    const float* fc_w1      = (const float*)d_in[3];
    const float* fc_b1      = (const float*)d_in[4];
    const float* fc_w2      = (const float*)d_in[5];
    const float* fc_b2      = (const float*)d_in[6];
    const float* mean_shift = (const float*)d_in[7];
    const float* aw         = (const float*)d_in[8];
    const float* ab         = (const float*)d_in[9];
    const int*   edge_index = (const int*)d_in[10];
    float* out = (float*)d_out;

    cudaFuncSetAttribute(gemm1_kernel, cudaFuncAttributeMaxDynamicSharedMemorySize, (int)G1_SMEM);
    cudaFuncSetAttribute(edge_kernel,  cudaFuncAttributeMaxDynamicSharedMemorySize, (int)EDGE_SMEM);

    gemm1_kernel<<<N_EDGES / 128, 256, G1_SMEM>>>(edge_attr, fc_w1, fc_b1, fc_w2);
    edge_kernel<<<NTILES, 256, EDGE_SMEM>>>(node_attr, edge_sh, fc_b2, edge_index);
    node_kernel<<<(N_NODES * 32 + 255) / 256, 256>>>(node_attr, mean_shift, aw, ab, out);
}

// round 11
// speedup vs baseline: 1.0269x; 1.0269x over previous
#include <cuda_runtime.h>
#include <cuda_fp16.h>
#include <cstdint>
#include <cstddef>

#define N_NODES 20000
#define N_EDGES 160000
#define MUL0 32
#define MUL1 16
#define NODE_DIM 80
#define EDGE_FEAT 128
#define HIDDEN 128
#define W_NUMEL 2560
#define MTILE 128
#define NTILES (N_EDGES / MTILE)      // 1250
#define NCHUNK 64
#define NCHUNKS (W_NUMEL / NCHUNK)    // 40

#define C0f   0.14433756729740643f
#define C1f   0.21650635094610965f
#define IS3f  0.5773502691896258f
#define IS6f  0.40824829046386296f
#define C0IS3 (C0f * IS3f)
#define C1IS3 (C1f * IS3f)
#define C1IS6 (C1f * IS6f)
#define EPS_LN 1e-5f

// ---------------- device scratch ----------------
__device__ __align__(16) __half g_Bf16[(size_t)W_NUMEL * HIDDEN];  // W2^T fp16 [n][k]
__device__ __align__(16) __half g_W1img[HIDDEN * 136];             // W1^T fp16, ROWB=272B image
__device__ float g_seg[(size_t)N_NODES * NODE_DIM];
__device__ float g_cnt[N_NODES];

// ---------------- PTX helpers ----------------
__device__ __forceinline__ uint32_t smem_u32(const void* p) {
    uint32_t a;
    asm("{ .reg .u64 t; cvta.to.shared.u64 t, %1; cvt.u32.u64 %0, t; }" : "=r"(a) : "l"(p));
    return a;
}
__device__ __forceinline__ void ldsm_x4(uint32_t* r, uint32_t addr) {
    asm volatile("ldmatrix.sync.aligned.m8n8.x4.shared.b16 {%0,%1,%2,%3}, [%4];"
        : "=r"(r[0]), "=r"(r[1]), "=r"(r[2]), "=r"(r[3]) : "r"(addr));
}
__device__ __forceinline__ void mma_f16(float* c, const uint32_t* a, uint32_t b0, uint32_t b1) {
    asm volatile("mma.sync.aligned.m16n8k16.row.col.f32.f16.f16.f32 "
        "{%0,%1,%2,%3}, {%4,%5,%6,%7}, {%8,%9}, {%0,%1,%2,%3};"
        : "+f"(c[0]), "+f"(c[1]), "+f"(c[2]), "+f"(c[3])
        : "r"(a[0]), "r"(a[1]), "r"(a[2]), "r"(a[3]), "r"(b0), "r"(b1));
}
__device__ __forceinline__ void cp_async16(uint32_t smem_addr, const void* gptr) {
    asm volatile("cp.async.ca.shared.global [%0], [%1], 16;" :: "r"(smem_addr), "l"(gptr));
}
#define CP_COMMIT() asm volatile("cp.async.commit_group;" ::: "memory")
#define CP_WAIT_0() asm volatile("cp.async.wait_group 0;" ::: "memory")

#define ROWB 272

// ---------------- prep: zero scratch, W2^T via coalesced SMEM transpose, W1 image ----------------
__global__ void prep_kernel(const float* __restrict__ fc_w1,
                            const float* __restrict__ fc_w2) {
    __shared__ float tile[64 * 65];
    const int tid = threadIdx.x;
    const int bid = blockIdx.x;
    const int gid = bid * 256 + tid;
    const int gsz = gridDim.x * 256;

    for (int i = gid; i < N_NODES * NODE_DIM; i += gsz) g_seg[i] = 0.0f;
    for (int i = gid; i < N_NODES; i += gsz) g_cnt[i] = 0.0f;

    if (bid < 80) {
        // transpose one 64(k) x 64(n) tile of fc_w2 -> g_Bf16[n][k]
        const int kt = bid / 40, nt = bid % 40;
#pragma unroll
        for (int it = 0; it < 16; it++) {
            const int i = tid + it * 256;          // 0..4095
            const int r = i >> 6, cc = i & 63;
            tile[r * 65 + cc] = fc_w2[(size_t)(kt * 64 + r) * W_NUMEL + nt * 64 + cc];
        }
        __syncthreads();
#pragma unroll
        for (int it = 0; it < 16; it++) {
            const int i = tid + it * 256;
            const int nn = i >> 6, kk = i & 63;
            g_Bf16[(size_t)(nt * 64 + nn) * HIDDEN + kt * 64 + kk] =
                __float2half_rn(tile[kk * 65 + nn]);
        }
    } else if (bid == 80) {
        // W1 image: fc_w1[k][n] -> g_W1img[n*136 + k] (tiny; coalesced read)
        for (int i = tid; i < HIDDEN * HIDDEN; i += 256) {
            const int k = i >> 7, n = i & 127;
            g_W1img[n * 136 + k] = __float2half_rn(fc_w1[i]);
        }
    }
}

// ---------------- fused edge kernel: GEMM1 prologue + GEMM2 chunk loop + TP + scatter ----------------
// Steady SMEM: A(h)[128][272]@0, B 2x[64][272]@34816, x0s@69632, x1s@86528,
//              shs@111616, srcs@113664 => 114176
// Prologue overlays: attr fp32 @[0,65536) ; W1 image @69632 (consumed before x0s gather)
#define OFF_A   0
#define OFF_B   34816
#define BBUF    17408
#define OFF_X0  69632
#define OFF_X1  86528
#define OFF_SH  111616
#define OFF_SRC 113664
#define EDGE_SMEM 114176

__global__ __launch_bounds__(256, 2)
void edge_kernel(const float* __restrict__ node_attr,
                 const float* __restrict__ edge_attr,
                 const float* __restrict__ edge_sh,
                 const float* __restrict__ fc_b1,
                 const float* __restrict__ fc_b2,
                 const int*   __restrict__ edge_index) {
    extern __shared__ char smc[];
    const uint32_t smb = smem_u32(smc);
    float* x0s = (float*)(smc + OFF_X0);
    float* x1s = (float*)(smc + OFF_X1);
    float* shs = (float*)(smc + OFF_SH);
    int*  srcs = (int*)(smc + OFF_SRC);

    const int tid  = threadIdx.x;
    const int w    = tid >> 5;          // warp -> rows 16w..16w+15
    const int lane = tid & 31;
    const int e0 = blockIdx.x * MTILE;

    const int q2 = 2 * (lane & 3);
    const int r8 = lane >> 2;
    const int mA = 16 * w + r8;         // rows mA, mA+8

    // ======== PROLOGUE: compute h = relu(edge_attr @ W1 + b1) in SMEM ========
    // 1) load attr fp32 [128][128] -> smem [0,65536) linear; W1 image -> OFF_X0
#pragma unroll
    for (int it = 0; it < 16; it++) {
        const int i = tid + it * 256;           // 0..4095 float4s
        cp_async16(smb + (uint32_t)i * 16,
                   edge_attr + (size_t)e0 * EDGE_FEAT + (size_t)i * 4);
    }
#pragma unroll
    for (int it = 0; it < 9; it++) {
        const int i = tid + it * 256;           // 0..2175 (34816/16)
        if (i < 2176)
            cp_async16(smb + OFF_X0 + (uint32_t)i * 16, (const char*)g_W1img + i * 16);
    }
    CP_COMMIT();
    CP_WAIT_0();
    __syncthreads();

    // 2) stage attr to regs, then rewrite as fp16 hi/lo (hi->region A, lo->region B)
    {
        float4 st[16];
#pragma unroll
        for (int it = 0; it < 16; it++)
            st[it] = *(const float4*)(smc + (size_t)(tid + it * 256) * 16);
        __syncthreads();
#pragma unroll
        for (int it = 0; it < 16; it++) {
            const int i = tid + it * 256;
            const int row = i >> 5, kc4 = i & 31;
            const float4 v = st[it];
            const __half hx = __float2half_rn(v.x), hy = __float2half_rn(v.y);
            const __half hz = __float2half_rn(v.z), hw = __float2half_rn(v.w);
            const __half lx = __float2half_rn(v.x - __half2float(hx));
            const __half ly = __float2half_rn(v.y - __half2float(hy));
            const __half lz = __float2half_rn(v.z - __half2float(hz));
            const __half lw = __float2half_rn(v.w - __half2float(hw));
            char* dh = smc + OFF_A + row * ROWB + kc4 * 8;
            char* dl = smc + OFF_B + row * ROWB + kc4 * 8;
            *(__half2*)(dh)     = __halves2half2(hx, hy);
            *(__half2*)(dh + 4) = __halves2half2(hz, hw);
            *(__half2*)(dl)     = __halves2half2(lx, ly);
            *(__half2*)(dl + 4) = __halves2half2(lz, lw);
        }
    }
    __syncthreads();

    // 3) 2-pass mma: c = attr_hi@W1 + attr_lo@W1
    const uint32_t aRow = (uint32_t)(16 * w + (lane & 7) + ((lane >> 3) & 1) * 8);
    const uint32_t aK = (uint32_t)(((lane >> 4) & 1) * 16);
    const uint32_t bRow = (uint32_t)((lane & 7) + ((lane >> 4) & 1) * 8);
    const uint32_t bK = (uint32_t)(((lane >> 3) & 1) * 16);
    {
        const uint32_t aHiB = smb + OFF_A + aRow * ROWB + aK;
        const uint32_t aLoB = smb + OFF_B + aRow * ROWB + aK;
        const uint32_t wB = smb + OFF_X0 + bRow * ROWB + bK;

        float c[16][4];
#pragma unroll
        for (int t = 0; t < 16; t++)
#pragma unroll
            for (int i = 0; i < 4; i++) c[t][i] = 0.0f;

#pragma unroll
        for (int ks = 0; ks < 8; ks++) {
            uint32_t ah[4], al[4];
            ldsm_x4(ah, aHiB + ks * 32);
            ldsm_x4(al, aLoB + ks * 32);
#pragma unroll
            for (int tp = 0; tp < 8; tp++) {
                uint32_t wf[4];
                ldsm_x4(wf, wB + tp * (16 * ROWB) + ks * 32);
                mma_f16(c[2 * tp],     ah, wf[0], wf[1]);
                mma_f16(c[2 * tp],     al, wf[0], wf[1]);
                mma_f16(c[2 * tp + 1], ah, wf[2], wf[3]);
                mma_f16(c[2 * tp + 1], al, wf[2], wf[3]);
            }
        }
        __syncthreads();   // all mma reads of attr_lo / W1 regions done

        // 4) bias + relu -> h fp16 into region A (own-warp rows only: safe WAR)
#pragma unroll
        for (int t = 0; t < 16; t++) {
            const int col = 8 * t + q2;
            const float2 b1v = __ldg((const float2*)(fc_b1 + col));
#pragma unroll
            for (int rr = 0; rr < 2; rr++) {
                const int mm = mA + 8 * rr;
                const float v0 = fmaxf(c[t][2 * rr + 0] + b1v.x, 0.0f);
                const float v1 = fmaxf(c[t][2 * rr + 1] + b1v.y, 0.0f);
                *(__half2*)(smc + OFF_A + mm * ROWB + col * 2) =
                    __halves2half2(__float2half_rn(v0), __float2half_rn(v1));
            }
        }
    }

    // 5) gather per-edge vectors (overwrites W1 region) + B chunk 0 cp.async
#pragma unroll
    for (int it = 0; it < 4; it++) {
        const int i = tid + it * 256;           // 0..1023 = row(64) x kc(16)
        const int row = i >> 4, kc = i & 15;
        cp_async16(smb + OFF_B + row * ROWB + kc * 16,
                   g_Bf16 + (size_t)row * HIDDEN + kc * 8);
    }
    CP_COMMIT();

    if (tid < MTILE) {
        const int eg  = e0 + tid;
        const int src = edge_index[eg];
        const int dst = edge_index[N_EDGES + eg];
        srcs[tid] = src;
        atomicAdd(&g_cnt[src], 1.0f);
        const float4* na = (const float4*)(node_attr + (size_t)dst * NODE_DIM);
#pragma unroll
        for (int q = 0; q < 8; q++) {
            const float4 v = na[q];
            x0s[tid * 33 + 4 * q + 0] = v.x;
            x0s[tid * 33 + 4 * q + 1] = v.y;
            x0s[tid * 33 + 4 * q + 2] = v.z;
            x0s[tid * 33 + 4 * q + 3] = v.w;
        }
#pragma unroll
        for (int q = 0; q < 12; q++) {
            const float4 v = na[8 + q];
            x1s[tid * 49 + 4 * q + 0] = v.x;
            x1s[tid * 49 + 4 * q + 1] = v.y;
            x1s[tid * 49 + 4 * q + 2] = v.z;
            x1s[tid * 49 + 4 * q + 3] = v.w;
        }
        const float4 sh4 = *(const float4*)(edge_sh + (size_t)eg * 4);
        shs[tid * 4 + 0] = sh4.x;
        shs[tid * 4 + 1] = sh4.y;
        shs[tid * 4 + 2] = sh4.z;
        shs[tid * 4 + 3] = sh4.w;
    }

    // ======== STEADY STATE: r6 champion loop, verbatim ========
    const uint32_t aB = smb + OFF_A + aRow * ROWB + aK;
    const uint32_t bBase0 = smb + OFF_B + bRow * ROWB + bK;

    float sh0r[2], sh1r[2][3];
#pragma unroll
    for (int rr = 0; rr < 2; rr++) { sh0r[rr] = 0.f; sh1r[rr][0] = sh1r[rr][1] = sh1r[rr][2] = 0.f; }

    float accO[2][8], accT3[2][4], accV[2][4][3];
#pragma unroll
    for (int rr = 0; rr < 2; rr++) {
#pragma unroll
        for (int i = 0; i < 8; i++) accO[rr][i] = 0.0f;
#pragma unroll
        for (int i = 0; i < 4; i++) {
            accT3[rr][i] = 0.0f;
#pragma unroll
            for (int k = 0; k < 3; k++) accV[rr][i][k] = 0.0f;
        }
    }

    bool shLoaded = false;

    for (int j = 0; j < NCHUNKS; j++) {
        CP_WAIT_0();
        __syncthreads();
        if (!shLoaded) {
#pragma unroll
            for (int rr = 0; rr < 2; rr++) {
                const int mm = mA + 8 * rr;
                sh0r[rr] = shs[mm * 4 + 0];
                sh1r[rr][0] = shs[mm * 4 + 1];
                sh1r[rr][1] = shs[mm * 4 + 2];
                sh1r[rr][2] = shs[mm * 4 + 3];
            }
            shLoaded = true;
        }
        // prefetch chunk j+1
        if (j + 1 < NCHUNKS) {
            const uint32_t sb = smb + OFF_B + ((j + 1) & 1) * BBUF;
            const __half* gp0 = g_Bf16 + (size_t)(j + 1) * NCHUNK * HIDDEN;
#pragma unroll
            for (int it = 0; it < 4; it++) {
                const int i = tid + it * 256;
                const int row = i >> 4, kc = i & 15;
                cp_async16(sb + row * ROWB + kc * 16, gp0 + (size_t)row * HIDDEN + kc * 8);
            }
            CP_COMMIT();
        }

        // ---- MMA: rows [16w,16w+16) x all 64 chunk cols, single fp16 pass ----
        const uint32_t bb = bBase0 + (j & 1) * BBUF;
        float c[8][4];
#pragma unroll
        for (int t = 0; t < 8; t++)
#pragma unroll
            for (int i = 0; i < 4; i++) c[t][i] = 0.0f;

#pragma unroll
        for (int ks = 0; ks < 8; ks++) {
            uint32_t ah[4];
            ldsm_x4(ah, aB + ks * 32);
#pragma unroll
            for (int tp = 0; tp < 4; tp++) {
                uint32_t bf[4];
                ldsm_x4(bf, bb + tp * (16 * ROWB) + ks * 32);
                mma_f16(c[2 * tp],     ah, bf[0], bf[1]);
                mma_f16(c[2 * tp + 1], ah, bf[2], bf[3]);
            }
        }

        // ---- epilogue: two 32-col groups g = 2j, 2j+1 ----
#pragma unroll
        for (int gi = 0; gi < 2; gi++) {
            const int g = 2 * j + gi;
            const int t0 = 4 * gi;
            float b2v[4][2];
#pragma unroll
            for (int tt = 0; tt < 4; tt++) {
                const float2 bv = __ldg((const float2*)(fc_b2 + 32 * g + 8 * tt + q2));
                b2v[tt][0] = bv.x; b2v[tt][1] = bv.y;
            }

            if (g < 32) {                               // block1 -> out0 (u = g)
                float s[2];
#pragma unroll
                for (int rr = 0; rr < 2; rr++)
                    s[rr] = C0f * sh0r[rr] * x0s[(mA + 8 * rr) * 33 + g];
#pragma unroll
                for (int tt = 0; tt < 4; tt++) {
                    float* cc = c[t0 + tt];
                    accO[0][2 * tt]     += s[0] * (cc[0] + b2v[tt][0]);
                    accO[0][2 * tt + 1] += s[0] * (cc[1] + b2v[tt][1]);
                    accO[1][2 * tt]     += s[1] * (cc[2] + b2v[tt][0]);
                    accO[1][2 * tt + 1] += s[1] * (cc[3] + b2v[tt][1]);
                }
            } else if (g < 48) {                        // block2 -> out0 (u = g-32)
                const int u = g - 32;
                float s[2];
#pragma unroll
                for (int rr = 0; rr < 2; rr++) {
                    const int mm = mA + 8 * rr;
                    s[rr] = C0IS3 * (x1s[mm * 49 + 3 * u] * sh1r[rr][0]
                                   + x1s[mm * 49 + 3 * u + 1] * sh1r[rr][1]
                                   + x1s[mm * 49 + 3 * u + 2] * sh1r[rr][2]);
                }
#pragma unroll
                for (int tt = 0; tt < 4; tt++) {
                    float* cc = c[t0 + tt];
                    accO[0][2 * tt]     += s[0] * (cc[0] + b2v[tt][0]);
                    accO[0][2 * tt + 1] += s[0] * (cc[1] + b2v[tt][1]);
                    accO[1][2 * tt]     += s[1] * (cc[2] + b2v[tt][0]);
                    accO[1][2 * tt + 1] += s[1] * (cc[3] + b2v[tt][1]);
                }
            } else if (g < 64) {                        // block3 -> t3
                const int u0 = 2 * (g - 48);
                float s[2][2];
#pragma unroll
                for (int rr = 0; rr < 2; rr++) {
                    const int mm = mA + 8 * rr;
                    s[rr][0] = C1IS3 * x0s[mm * 33 + u0];
                    s[rr][1] = C1IS3 * x0s[mm * 33 + u0 + 1];
                }
#pragma unroll
                for (int tt = 0; tt < 4; tt++) {
                    const int us = tt >> 1;
                    const int sl = 2 * (tt & 1);
                    float* cc = c[t0 + tt];
                    accT3[0][sl]     += s[0][us] * (cc[0] + b2v[tt][0]);
                    accT3[0][sl + 1] += s[0][us] * (cc[1] + b2v[tt][1]);
                    accT3[1][sl]     += s[1][us] * (cc[2] + b2v[tt][0]);
                    accT3[1][sl + 1] += s[1][us] * (cc[3] + b2v[tt][1]);
                }
            } else {                                    // block4/5 -> out1
                const bool is5 = (g >= 72);
                const int u0 = is5 ? 2 * (g - 72) : 2 * (g - 64);
                float av[2][2][3];
#pragma unroll
                for (int rr = 0; rr < 2; rr++) {
                    const int mm = mA + 8 * rr;
#pragma unroll
                    for (int us = 0; us < 2; us++) {
                        const int u = u0 + us;
                        const float xx = x1s[mm * 49 + 3 * u + 0];
                        const float xy = x1s[mm * 49 + 3 * u + 1];
                        const float xz = x1s[mm * 49 + 3 * u + 2];
                        if (!is5) {
                            const float kb = C1IS3 * sh0r[rr];
                            av[rr][us][0] = kb * xx;
                            av[rr][us][1] = kb * xy;
                            av[rr][us][2] = kb * xz;
                        } else {
                            av[rr][us][0] = C1IS6 * (xy * sh1r[rr][2] - xz * sh1r[rr][1]);
                            av[rr][us][1] = C1IS6 * (xz * sh1r[rr][0] - xx * sh1r[rr][2]);
                            av[rr][us][2] = C1IS6 * (xx * sh1r[rr][1] - xy * sh1r[rr][0]);
                        }
                    }
                }
#pragma unroll
                for (int tt = 0; tt < 4; tt++) {
                    const int us = tt >> 1;
                    const int sl = 2 * (tt & 1);
                    float* cc = c[t0 + tt];
                    const float D00 = cc[0] + b2v[tt][0], D01 = cc[1] + b2v[tt][1];
                    const float D10 = cc[2] + b2v[tt][0], D11 = cc[3] + b2v[tt][1];
#pragma unroll
                    for (int k = 0; k < 3; k++) {
                        accV[0][sl][k]     += av[0][us][k] * D00;
                        accV[0][sl + 1][k] += av[0][us][k] * D01;
                        accV[1][sl][k]     += av[1][us][k] * D10;
                        accV[1][sl + 1][k] += av[1][us][k] * D11;
                    }
                }
            }
        }
    }

    // ---- scatter ----
#pragma unroll
    for (int rr = 0; rr < 2; rr++) {
        const int mm = mA + 8 * rr;
        const int src = srcs[mm];
        float* segp = g_seg + (size_t)src * NODE_DIM;
#pragma unroll
        for (int t = 0; t < 4; t++)
#pragma unroll
            for (int b = 0; b < 2; b++)
                atomicAdd(segp + 8 * t + q2 + b, accO[rr][2 * t + b]);
#pragma unroll
        for (int ws = 0; ws < 2; ws++)
#pragma unroll
            for (int b = 0; b < 2; b++) {
                const int wc = 8 * ws + q2 + b;
#pragma unroll
                for (int k = 0; k < 3; k++)
                    atomicAdd(segp + 32 + 3 * wc + k,
                              fmaf(sh1r[rr][k], accT3[rr][2 * ws + b], accV[rr][2 * ws + b][k]));
            }
    }
}

// ---------------- node epilogue ----------------
__global__ void node_kernel(const float* __restrict__ node_attr,
                            const float* __restrict__ mean_shift,
                            const float* __restrict__ aw,
                            const float* __restrict__ ab,
                            float* __restrict__ out) {
    const int warp = (blockIdx.x * blockDim.x + threadIdx.x) >> 5;
    const int lane = threadIdx.x & 31;
    if (warp >= N_NODES) return;
    const unsigned full = 0xFFFFFFFFu;

    const float inv = 1.0f / fmaxf(g_cnt[warp], 1.0f);
    const float* seg = g_seg + (size_t)warp * NODE_DIM;
    const float* na  = node_attr + (size_t)warp * NODE_DIM;

    float o0 = seg[lane] * inv + na[lane];
    float mval = o0;
#pragma unroll
    for (int off = 16; off; off >>= 1) mval += __shfl_xor_sync(full, mval, off);
    mval *= (1.0f / 32.0f);
    const float f0 = o0 - mval * mean_shift[lane];
    float s = f0 * f0;
#pragma unroll
    for (int off = 16; off; off >>= 1) s += __shfl_xor_sync(full, s, off);
    const float sc0 = rsqrtf(s * (1.0f / 32.0f) + EPS_LN) * aw[lane];
    out[(size_t)warp * NODE_DIM + lane] = f0 * sc0 + ab[lane];

    float vx = 0.0f, vy = 0.0f, vz = 0.0f, msv = 0.0f;
    if (lane < 16) {
        vx = seg[32 + 3 * lane + 0] * inv + na[32 + 3 * lane + 0];
        vy = seg[32 + 3 * lane + 1] * inv + na[32 + 3 * lane + 1];
        vz = seg[32 + 3 * lane + 2] * inv + na[32 + 3 * lane + 2];
        msv = mean_shift[32 + lane];
    }
    float mx = vx, my = vy, mz = vz;
#pragma unroll
    for (int off = 16; off; off >>= 1) {
        mx += __shfl_xor_sync(full, mx, off);
        my += __shfl_xor_sync(full, my, off);
        mz += __shfl_xor_sync(full, mz, off);
    }
    mx *= (1.0f / 16.0f); my *= (1.0f / 16.0f); mz *= (1.0f / 16.0f);
    const float fx = vx - mx * msv;
    const float fy = vy - my * msv;
    const float fz = vz - mz * msv;
    float sq = (lane < 16) ? (fx * fx + fy * fy + fz * fz) : 0.0f;
#pragma unroll
    for (int off = 16; off; off >>= 1) sq += __shfl_xor_sync(full, sq, off);
    if (lane < 16) {
        const float sc1 = rsqrtf(sq * (1.0f / 48.0f) + EPS_LN) * aw[32 + lane];
        out[(size_t)warp * NODE_DIM + 32 + 3 * lane + 0] = fx * sc1;
        out[(size_t)warp * NODE_DIM + 32 + 3 * lane + 1] = fy * sc1;
        out[(size_t)warp * NODE_DIM + 32 + 3 * lane + 2] = fz * sc1;
    }
}

// ---------------- launch ----------------
extern "C" void kernel_launch(void* const* d_in, const int* in_sizes, int n_in,
                              void* d_out, int out_size) {
    const float* node_attr  = (const float*)d_in[0];
    const float* edge_attr  = (const float*)d_in[1];
    const float* edge_sh    = (const float*)d_in[2];
    const float* fc_w1      = (const float*)d_in[3];
    const float* fc_b1      = (const float*)d_in[4];
    const float* fc_w2      = (const float*)d_in[5];
    const float* fc_b2      = (const float*)d_in[6];
    const float* mean_shift = (const float*)d_in[7];
    const float* aw         = (const float*)d_in[8];
    const float* ab         = (const float*)d_in[9];
    const int*   edge_index = (const int*)d_in[10];
    float* out = (float*)d_out;

    cudaFuncSetAttribute(edge_kernel, cudaFuncAttributeMaxDynamicSharedMemorySize, (int)EDGE_SMEM);

    prep_kernel<<<160, 256>>>(fc_w1, fc_w2);
    edge_kernel<<<NTILES, 256, EDGE_SMEM>>>(node_attr, edge_attr, edge_sh, fc_b1, fc_b2, edge_index);
    node_kernel<<<(N_NODES * 32 + 255) / 256, 256>>>(node_attr, mean_shift, aw, ab, out);
}

// round 12
// speedup vs baseline: 1.1381x; 1.1083x over previous
#include <cuda_runtime.h>
#include <cuda_fp16.h>
#include <cstdint>
#include <cstddef>

#define N_NODES 20000
#define N_EDGES 160000
#define MUL0 32
#define MUL1 16
#define NODE_DIM 80
#define EDGE_FEAT 128
#define HIDDEN 128
#define W_NUMEL 2560
#define MTILE 128
#define NTILES (N_EDGES / MTILE)      // 1250
#define NCHUNK 64
#define NCHUNKS (W_NUMEL / NCHUNK)    // 40
#define ETHREADS 128

#define C0f   0.14433756729740643f
#define C1f   0.21650635094610965f
#define IS3f  0.5773502691896258f
#define IS6f  0.40824829046386296f
#define C0IS3 (C0f * IS3f)
#define C1IS3 (C1f * IS3f)
#define C1IS6 (C1f * IS6f)
#define EPS_LN 1e-5f

// ---------------- device scratch ----------------
__device__ __align__(16) __half g_Bf16[(size_t)W_NUMEL * HIDDEN];  // W2^T fp16 [n][k]
__device__ __align__(16) __half g_W1img[HIDDEN * 136];             // W1^T fp16 image (ROWB layout)
__device__ float g_seg[(size_t)N_NODES * NODE_DIM];
__device__ float g_cnt[N_NODES];

// ---------------- PTX helpers ----------------
__device__ __forceinline__ uint32_t smem_u32(const void* p) {
    uint32_t a;
    asm("{ .reg .u64 t; cvta.to.shared.u64 t, %1; cvt.u32.u64 %0, t; }" : "=r"(a) : "l"(p));
    return a;
}
__device__ __forceinline__ void ldsm_x4(uint32_t* r, uint32_t addr) {
    asm volatile("ldmatrix.sync.aligned.m8n8.x4.shared.b16 {%0,%1,%2,%3}, [%4];"
        : "=r"(r[0]), "=r"(r[1]), "=r"(r[2]), "=r"(r[3]) : "r"(addr));
}
__device__ __forceinline__ void mma_f16(float* c, const uint32_t* a, uint32_t b0, uint32_t b1) {
    asm volatile("mma.sync.aligned.m16n8k16.row.col.f32.f16.f16.f32 "
        "{%0,%1,%2,%3}, {%4,%5,%6,%7}, {%8,%9}, {%0,%1,%2,%3};"
        : "+f"(c[0]), "+f"(c[1]), "+f"(c[2]), "+f"(c[3])
        : "r"(a[0]), "r"(a[1]), "r"(a[2]), "r"(a[3]), "r"(b0), "r"(b1));
}
__device__ __forceinline__ void cp_async16(uint32_t smem_addr, const void* gptr) {
    asm volatile("cp.async.ca.shared.global [%0], [%1], 16;" :: "r"(smem_addr), "l"(gptr));
}
#define CP_COMMIT() asm volatile("cp.async.commit_group;" ::: "memory")
#define CP_WAIT_0() asm volatile("cp.async.wait_group 0;" ::: "memory")

#define ROWB 272

// ---------------- prep: zero scratch, W2^T coalesced transpose, W1 image ----------------
__global__ void prep_kernel(const float* __restrict__ fc_w1,
                            const float* __restrict__ fc_w2) {
    __shared__ float tile[64 * 65];
    const int tid = threadIdx.x;
    const int bid = blockIdx.x;
    const int gid = bid * 256 + tid;
    const int gsz = gridDim.x * 256;

    for (int i = gid; i < N_NODES * NODE_DIM; i += gsz) g_seg[i] = 0.0f;
    for (int i = gid; i < N_NODES; i += gsz) g_cnt[i] = 0.0f;

    if (bid < 80) {
        const int kt = bid / 40, nt = bid % 40;
#pragma unroll
        for (int it = 0; it < 16; it++) {
            const int i = tid + it * 256;
            const int r = i >> 6, cc = i & 63;
            tile[r * 65 + cc] = fc_w2[(size_t)(kt * 64 + r) * W_NUMEL + nt * 64 + cc];
        }
        __syncthreads();
#pragma unroll
        for (int it = 0; it < 16; it++) {
            const int i = tid + it * 256;
            const int nn = i >> 6, kk = i & 63;
            g_Bf16[(size_t)(nt * 64 + nn) * HIDDEN + kt * 64 + kk] =
                __float2half_rn(tile[kk * 65 + nn]);
        }
    } else if (bid == 80) {
        for (int i = tid; i < HIDDEN * HIDDEN; i += 256) {
            const int k = i >> 7, n = i & 127;
            g_W1img[n * 136 + k] = __float2half_rn(fc_w1[i]);
        }
    }
}

// ---------------- fused edge kernel: 128 threads, A-in-regs, B dup 4x, 2 CTA/SM ----------------
// Steady SMEM: h[128][272]@0 (34816), B stage0@34816, stage1@52224,
//              x0s@69632, x1s@86528, shs@111616, srcs@113664 => 114176
// Prologue overlays: attr-hi -> region A, attr-lo -> B stages region, W1 -> x0 region
#define OFF_A   0
#define OFF_B   34816
#define BBUF    17408
#define OFF_X0  69632
#define OFF_X1  86528
#define OFF_SH  111616
#define OFF_SRC 113664
#define EDGE_SMEM 114176

__global__ __launch_bounds__(ETHREADS, 2)
void edge_kernel(const float* __restrict__ node_attr,
                 const float* __restrict__ edge_attr,
                 const float* __restrict__ edge_sh,
                 const float* __restrict__ fc_b1,
                 const float* __restrict__ fc_b2,
                 const int*   __restrict__ edge_index) {
    extern __shared__ char smc[];
    const uint32_t smb = smem_u32(smc);
    float* x0s = (float*)(smc + OFF_X0);
    float* x1s = (float*)(smc + OFF_X1);
    float* shs = (float*)(smc + OFF_SH);
    int*  srcs = (int*)(smc + OFF_SRC);

    const int tid  = threadIdx.x;
    const int w    = tid >> 5;          // warp 0..3 -> rows 32w..32w+31
    const int lane = tid & 31;
    const int e0 = blockIdx.x * MTILE;

    const int q2 = 2 * (lane & 3);
    const int r8 = lane >> 2;

    // lane mapping for ldsm
    const uint32_t aRowLoc = (uint32_t)((lane & 7) + 8 * ((lane >> 3) & 1));
    const uint32_t aK = (uint32_t)(16 * ((lane >> 4) & 1));
    const uint32_t bRow = (uint32_t)((lane & 7) + 8 * ((lane >> 4) & 1));
    const uint32_t bK = (uint32_t)(16 * ((lane >> 3) & 1));

    // ======== PROLOGUE: h = relu(edge_attr @ W1 + b1) in SMEM ========
    // W1 image -> x0 region via cp.async
#pragma unroll
    for (int it = 0; it < 17; it++) {
        const int i = tid + it * ETHREADS;       // 0..2175
        if (i < 2176)
            cp_async16(smb + OFF_X0 + (uint32_t)i * 16, (const char*)g_W1img + i * 16);
    }
    CP_COMMIT();

    // attr: per-warp row-cooperative LDG.128 -> fp16 hi/lo STS (own 32 rows)
    {
        const float4* ga = (const float4*)(edge_attr + (size_t)e0 * EDGE_FEAT);
#pragma unroll 4
        for (int r = 0; r < 32; r++) {
            const int row = 32 * w + r;
            const float4 v = ga[(size_t)row * 32 + lane];
            const __half hx = __float2half_rn(v.x), hy = __float2half_rn(v.y);
            const __half hz = __float2half_rn(v.z), hw = __float2half_rn(v.w);
            const __half lx = __float2half_rn(v.x - __half2float(hx));
            const __half ly = __float2half_rn(v.y - __half2float(hy));
            const __half lz = __float2half_rn(v.z - __half2float(hz));
            const __half lw = __float2half_rn(v.w - __half2float(hw));
            char* dh = smc + OFF_A + row * ROWB + lane * 8;
            char* dl = smc + OFF_B + row * ROWB + lane * 8;
            *(__half2*)(dh)     = __halves2half2(hx, hy);
            *(__half2*)(dh + 4) = __halves2half2(hz, hw);
            *(__half2*)(dl)     = __halves2half2(lx, ly);
            *(__half2*)(dl + 4) = __halves2half2(lz, lw);
        }
    }
    CP_WAIT_0();          // W1 landed
    __syncthreads();      // W1 visible to all; attr own-rows self-consistent

    // prologue mma: two 16-row passes per warp (2-pass hi/lo x W1), h -> region A
    {
        const uint32_t wB = smb + OFF_X0 + bRow * ROWB + bK;
#pragma unroll
        for (int rt = 0; rt < 2; rt++) {
            const uint32_t aHiB = smb + OFF_A + ((uint32_t)(32 * w + 16 * rt) + aRowLoc) * ROWB + aK;
            const uint32_t aLoB = smb + OFF_B + ((uint32_t)(32 * w + 16 * rt) + aRowLoc) * ROWB + aK;
            float c[16][4];
#pragma unroll
            for (int t = 0; t < 16; t++)
#pragma unroll
                for (int i = 0; i < 4; i++) c[t][i] = 0.0f;
#pragma unroll
            for (int ks = 0; ks < 8; ks++) {
                uint32_t ah[4], al[4];
                ldsm_x4(ah, aHiB + ks * 32);
                ldsm_x4(al, aLoB + ks * 32);
#pragma unroll
                for (int tp = 0; tp < 8; tp++) {
                    uint32_t wf[4];
                    ldsm_x4(wf, wB + tp * (16 * ROWB) + ks * 32);
                    mma_f16(c[2 * tp],     ah, wf[0], wf[1]);
                    mma_f16(c[2 * tp],     al, wf[0], wf[1]);
                    mma_f16(c[2 * tp + 1], ah, wf[2], wf[3]);
                    mma_f16(c[2 * tp + 1], al, wf[2], wf[3]);
                }
            }
            // bias + relu -> h fp16 (own rows; same-warp WAR on attr-hi rows is safe)
#pragma unroll
            for (int t = 0; t < 16; t++) {
                const int col = 8 * t + q2;
                const float2 b1v = __ldg((const float2*)(fc_b1 + col));
#pragma unroll
                for (int rr = 0; rr < 2; rr++) {
                    const int mm = 32 * w + 16 * rt + 8 * rr + r8;
                    const float v0 = fmaxf(c[t][2 * rr + 0] + b1v.x, 0.0f);
                    const float v1 = fmaxf(c[t][2 * rr + 1] + b1v.y, 0.0f);
                    *(__half2*)(smc + OFF_A + mm * ROWB + col * 2) =
                        __halves2half2(__float2half_rn(v0), __float2half_rn(v1));
                }
            }
        }
    }
    __syncwarp();

    // A frags -> registers (permanent)
    uint32_t a_[2][8][4];
#pragma unroll
    for (int rt = 0; rt < 2; rt++) {
        const uint32_t base = smb + OFF_A + ((uint32_t)(32 * w + 16 * rt) + aRowLoc) * ROWB + aK;
#pragma unroll
        for (int ks = 0; ks < 8; ks++)
            ldsm_x4(a_[rt][ks], base + ks * 32);
    }
    __syncthreads();      // everyone done with attr-lo (B region) + W1 (x0 region)

    // B chunk 0 prefetch + gather tables
#pragma unroll
    for (int it = 0; it < 8; it++) {
        const int i = tid + it * ETHREADS;       // 0..1023 = row(64) x kc(16)
        const int row = i >> 4, kc = i & 15;
        cp_async16(smb + OFF_B + row * ROWB + kc * 16,
                   g_Bf16 + (size_t)row * HIDDEN + kc * 8);
    }
    CP_COMMIT();

    {
        const int eg  = e0 + tid;
        const int src = edge_index[eg];
        const int dst = edge_index[N_EDGES + eg];
        srcs[tid] = src;
        atomicAdd(&g_cnt[src], 1.0f);
        const float4* na = (const float4*)(node_attr + (size_t)dst * NODE_DIM);
#pragma unroll
        for (int q = 0; q < 8; q++) {
            const float4 v = na[q];
            x0s[tid * 33 + 4 * q + 0] = v.x;
            x0s[tid * 33 + 4 * q + 1] = v.y;
            x0s[tid * 33 + 4 * q + 2] = v.z;
            x0s[tid * 33 + 4 * q + 3] = v.w;
        }
#pragma unroll
        for (int q = 0; q < 12; q++) {
            const float4 v = na[8 + q];
            x1s[tid * 49 + 4 * q + 0] = v.x;
            x1s[tid * 49 + 4 * q + 1] = v.y;
            x1s[tid * 49 + 4 * q + 2] = v.z;
            x1s[tid * 49 + 4 * q + 3] = v.w;
        }
        const float4 sh4 = *(const float4*)(edge_sh + (size_t)eg * 4);
        shs[tid * 4 + 0] = sh4.x;
        shs[tid * 4 + 1] = sh4.y;
        shs[tid * 4 + 2] = sh4.z;
        shs[tid * 4 + 3] = sh4.w;
    }

    // ======== STEADY STATE ========
    const uint32_t bRowOff = bRow * ROWB + bK;
    int mmr[4];
#pragma unroll
    for (int r = 0; r < 4; r++) mmr[r] = 32 * w + 16 * (r >> 1) + 8 * (r & 1) + r8;

    float sh0r[4], sh1r[4][3];
    bool shLoaded = false;

#define CHUNK_TOP(j) \
    CP_WAIT_0(); \
    __syncthreads(); \
    if ((j) + 1 < NCHUNKS) { \
        const uint32_t sb = smb + OFF_B + (uint32_t)((((j) + 1) & 1) * BBUF); \
        const __half* gp0 = g_Bf16 + (size_t)((j) + 1) * NCHUNK * HIDDEN; \
        _Pragma("unroll") \
        for (int it = 0; it < 8; it++) { \
            const int i = tid + it * ETHREADS; \
            const int row = i >> 4, kc = i & 15; \
            cp_async16(sb + row * ROWB + kc * 16, gp0 + (size_t)row * HIDDEN + kc * 8); \
        } \
        CP_COMMIT(); \
    }

#define LOAD_SH() \
    if (!shLoaded) { \
        _Pragma("unroll") for (int r = 0; r < 4; r++) { \
            sh0r[r] = shs[mmr[r] * 4 + 0]; \
            sh1r[r][0] = shs[mmr[r] * 4 + 1]; \
            sh1r[r][1] = shs[mmr[r] * 4 + 2]; \
            sh1r[r][2] = shs[mmr[r] * 4 + 3]; \
        } \
        shLoaded = true; \
    }

// 32 rows x 64 cols; A from regs, B from stage (j&1); all mma before any c read
#define CHUNK_MMA(j) \
    float c2[2][8][4]; \
    { \
        _Pragma("unroll") for (int rt = 0; rt < 2; rt++) \
        _Pragma("unroll") for (int t = 0; t < 8; t++) \
        _Pragma("unroll") for (int i = 0; i < 4; i++) c2[rt][t][i] = 0.0f; \
        const uint32_t bb = smb + OFF_B + (uint32_t)(((j) & 1) * BBUF) + bRowOff; \
        _Pragma("unroll") for (int ks = 0; ks < 8; ks++) { \
            _Pragma("unroll") for (int tp = 0; tp < 4; tp++) { \
                uint32_t bf[4]; \
                ldsm_x4(bf, bb + tp * (16 * ROWB) + ks * 32); \
                mma_f16(c2[0][2 * tp],     a_[0][ks], bf[0], bf[1]); \
                mma_f16(c2[0][2 * tp + 1], a_[0][ks], bf[2], bf[3]); \
                mma_f16(c2[1][2 * tp],     a_[1][ks], bf[0], bf[1]); \
                mma_f16(c2[1][2 * tp + 1], a_[1][ks], bf[2], bf[3]); \
            } \
        } \
    }

    // ============ phase 1: j 0..23 (block1/block2 -> accO) ============
    {
        float accO[4][8];
#pragma unroll
        for (int r = 0; r < 4; r++)
#pragma unroll
            for (int i = 0; i < 8; i++) accO[r][i] = 0.0f;

        for (int j = 0; j < 24; j++) {
            CHUNK_TOP(j);
            LOAD_SH();
            CHUNK_MMA(j);
#pragma unroll
            for (int gi = 0; gi < 2; gi++) {
                const int g = 2 * j + gi;
                float s[4];
                if (g < 32) {
#pragma unroll
                    for (int r = 0; r < 4; r++)
                        s[r] = C0f * sh0r[r] * x0s[mmr[r] * 33 + g];
                } else {
                    const int u = g - 32;
#pragma unroll
                    for (int r = 0; r < 4; r++)
                        s[r] = C0IS3 * (x1s[mmr[r] * 49 + 3 * u]     * sh1r[r][0]
                                      + x1s[mmr[r] * 49 + 3 * u + 1] * sh1r[r][1]
                                      + x1s[mmr[r] * 49 + 3 * u + 2] * sh1r[r][2]);
                }
#pragma unroll
                for (int tt = 0; tt < 4; tt++) {
                    const float2 bv = __ldg((const float2*)(fc_b2 + 32 * g + 8 * tt + q2));
#pragma unroll
                    for (int rt = 0; rt < 2; rt++)
#pragma unroll
                        for (int rr = 0; rr < 2; rr++) {
                            const int r = 2 * rt + rr;
                            float* cc = c2[rt][4 * gi + tt];
                            accO[r][2 * tt]     += s[r] * (cc[2 * rr]     + bv.x);
                            accO[r][2 * tt + 1] += s[r] * (cc[2 * rr + 1] + bv.y);
                        }
                }
            }
        }
#pragma unroll
        for (int r = 0; r < 4; r++) {
            float* segp = g_seg + (size_t)srcs[mmr[r]] * NODE_DIM;
#pragma unroll
            for (int tt = 0; tt < 4; tt++)
#pragma unroll
                for (int b = 0; b < 2; b++)
                    atomicAdd(segp + 8 * tt + q2 + b, accO[r][2 * tt + b]);
        }
    }

    // ============ phase 2: j 24..31 (block3 -> t3) ============
    {
        float accT3[4][4];
#pragma unroll
        for (int r = 0; r < 4; r++)
#pragma unroll
            for (int i = 0; i < 4; i++) accT3[r][i] = 0.0f;

        for (int j = 24; j < 32; j++) {
            CHUNK_TOP(j);
            CHUNK_MMA(j);
#pragma unroll
            for (int gi = 0; gi < 2; gi++) {
                const int g = 2 * j + gi;
                const int u0 = 2 * (g - 48);
                float s[4][2];
#pragma unroll
                for (int r = 0; r < 4; r++) {
                    s[r][0] = C1IS3 * x0s[mmr[r] * 33 + u0];
                    s[r][1] = C1IS3 * x0s[mmr[r] * 33 + u0 + 1];
                }
#pragma unroll
                for (int tt = 0; tt < 4; tt++) {
                    const int us = tt >> 1;
                    const int sl = 2 * (tt & 1);
                    const float2 bv = __ldg((const float2*)(fc_b2 + 32 * g + 8 * tt + q2));
#pragma unroll
                    for (int rt = 0; rt < 2; rt++)
#pragma unroll
                        for (int rr = 0; rr < 2; rr++) {
                            const int r = 2 * rt + rr;
                            float* cc = c2[rt][4 * gi + tt];
                            accT3[r][sl]     += s[r][us] * (cc[2 * rr]     + bv.x);
                            accT3[r][sl + 1] += s[r][us] * (cc[2 * rr + 1] + bv.y);
                        }
                }
            }
        }
#pragma unroll
        for (int r = 0; r < 4; r++) {
            float* segp = g_seg + (size_t)srcs[mmr[r]] * NODE_DIM;
#pragma unroll
            for (int ws = 0; ws < 2; ws++)
#pragma unroll
                for (int b = 0; b < 2; b++) {
                    const int wc = 8 * ws + q2 + b;
                    const float t3 = accT3[r][2 * ws + b];
                    atomicAdd(segp + 32 + 3 * wc + 0, sh1r[r][0] * t3);
                    atomicAdd(segp + 32 + 3 * wc + 1, sh1r[r][1] * t3);
                    atomicAdd(segp + 32 + 3 * wc + 2, sh1r[r][2] * t3);
                }
        }
    }

    // ============ phase 3: j 32..39 (block4/5 -> V) ============
    {
        float accV[4][4][3];
#pragma unroll
        for (int r = 0; r < 4; r++)
#pragma unroll
            for (int i = 0; i < 4; i++)
#pragma unroll
                for (int k = 0; k < 3; k++) accV[r][i][k] = 0.0f;

        for (int j = 32; j < 40; j++) {
            CHUNK_TOP(j);
            CHUNK_MMA(j);
#pragma unroll
            for (int gi = 0; gi < 2; gi++) {
                const int g = 2 * j + gi;
                const bool is5 = (g >= 72);
                const int u0 = is5 ? 2 * (g - 72) : 2 * (g - 64);
                float av[4][2][3];
#pragma unroll
                for (int r = 0; r < 4; r++) {
#pragma unroll
                    for (int us = 0; us < 2; us++) {
                        const int u = u0 + us;
                        const float xx = x1s[mmr[r] * 49 + 3 * u + 0];
                        const float xy = x1s[mmr[r] * 49 + 3 * u + 1];
                        const float xz = x1s[mmr[r] * 49 + 3 * u + 2];
                        if (!is5) {
                            const float kb = C1IS3 * sh0r[r];
                            av[r][us][0] = kb * xx;
                            av[r][us][1] = kb * xy;
                            av[r][us][2] = kb * xz;
                        } else {
                            av[r][us][0] = C1IS6 * (xy * sh1r[r][2] - xz * sh1r[r][1]);
                            av[r][us][1] = C1IS6 * (xz * sh1r[r][0] - xx * sh1r[r][2]);
                            av[r][us][2] = C1IS6 * (xx * sh1r[r][1] - xy * sh1r[r][0]);
                        }
                    }
                }
#pragma unroll
                for (int tt = 0; tt < 4; tt++) {
                    const int us = tt >> 1;
                    const int sl = 2 * (tt & 1);
                    const float2 bv = __ldg((const float2*)(fc_b2 + 32 * g + 8 * tt + q2));
#pragma unroll
                    for (int rt = 0; rt < 2; rt++)
#pragma unroll
                        for (int rr = 0; rr < 2; rr++) {
                            const int r = 2 * rt + rr;
                            float* cc = c2[rt][4 * gi + tt];
                            const float D0 = cc[2 * rr] + bv.x;
                            const float D1 = cc[2 * rr + 1] + bv.y;
#pragma unroll
                            for (int k = 0; k < 3; k++) {
                                accV[r][sl][k]     += av[r][us][k] * D0;
                                accV[r][sl + 1][k] += av[r][us][k] * D1;
                            }
                        }
                }
            }
        }
#pragma unroll
        for (int r = 0; r < 4; r++) {
            float* segp = g_seg + (size_t)srcs[mmr[r]] * NODE_DIM;
#pragma unroll
            for (int ws = 0; ws < 2; ws++)
#pragma unroll
                for (int b = 0; b < 2; b++) {
                    const int wc = 8 * ws + q2 + b;
#pragma unroll
                    for (int k = 0; k < 3; k++)
                        atomicAdd(segp + 32 + 3 * wc + k, accV[r][2 * ws + b][k]);
                }
        }
    }
}

// ---------------- node epilogue ----------------
__global__ void node_kernel(const float* __restrict__ node_attr,
                            const float* __restrict__ mean_shift,
                            const float* __restrict__ aw,
                            const float* __restrict__ ab,
                            float* __restrict__ out) {
    const int warp = (blockIdx.x * blockDim.x + threadIdx.x) >> 5;
    const int lane = threadIdx.x & 31;
    if (warp >= N_NODES) return;
    const unsigned full = 0xFFFFFFFFu;

    const float inv = 1.0f / fmaxf(g_cnt[warp], 1.0f);
    const float* seg = g_seg + (size_t)warp * NODE_DIM;
    const float* na  = node_attr + (size_t)warp * NODE_DIM;

    float o0 = seg[lane] * inv + na[lane];
    float mval = o0;
#pragma unroll
    for (int off = 16; off; off >>= 1) mval += __shfl_xor_sync(full, mval, off);
    mval *= (1.0f / 32.0f);
    const float f0 = o0 - mval * mean_shift[lane];
    float s = f0 * f0;
#pragma unroll
    for (int off = 16; off; off >>= 1) s += __shfl_xor_sync(full, s, off);
    const float sc0 = rsqrtf(s * (1.0f / 32.0f) + EPS_LN) * aw[lane];
    out[(size_t)warp * NODE_DIM + lane] = f0 * sc0 + ab[lane];

    float vx = 0.0f, vy = 0.0f, vz = 0.0f, msv = 0.0f;
    if (lane < 16) {
        vx = seg[32 + 3 * lane + 0] * inv + na[32 + 3 * lane + 0];
        vy = seg[32 + 3 * lane + 1] * inv + na[32 + 3 * lane + 1];
        vz = seg[32 + 3 * lane + 2] * inv + na[32 + 3 * lane + 2];
        msv = mean_shift[32 + lane];
    }
    float mx = vx, my = vy, mz = vz;
#pragma unroll
    for (int off = 16; off; off >>= 1) {
        mx += __shfl_xor_sync(full, mx, off);
        my += __shfl_xor_sync(full, my, off);
        mz += __shfl_xor_sync(full, mz, off);
    }
    mx *= (1.0f / 16.0f); my *= (1.0f / 16.0f); mz *= (1.0f / 16.0f);
    const float fx = vx - mx * msv;
    const float fy = vy - my * msv;
    const float fz = vz - mz * msv;
    float sq = (lane < 16) ? (fx * fx + fy * fy + fz * fz) : 0.0f;
#pragma unroll
    for (int off = 16; off; off >>= 1) sq += __shfl_xor_sync(full, sq, off);
    if (lane < 16) {
        const float sc1 = rsqrtf(sq * (1.0f / 48.0f) + EPS_LN) * aw[32 + lane];
        out[(size_t)warp * NODE_DIM + 32 + 3 * lane + 0] = fx * sc1;
        out[(size_t)warp * NODE_DIM + 32 + 3 * lane + 1] = fy * sc1;
        out[(size_t)warp * NODE_DIM + 32 + 3 * lane + 2] = fz * sc1;
    }
}

// ---------------- launch ----------------
extern "C" void kernel_launch(void* const* d_in, const int* in_sizes, int n_in,
                              void* d_out, int out_size) {
    const float* node_attr  = (const float*)d_in[0];
    const float* edge_attr  = (const float*)d_in[1];
    const float* edge_sh    = (const float*)d_in[2];
    const float* fc_w1      = (const float*)d_in[3];
    const float* fc_b1      = (const float*)d_in[4];
    const float* fc_w2      = (const float*)d_in[5];
    const float* fc_b2      = (const float*)d_in[6];
    const float* mean_shift = (const float*)d_in[7];
    const float* aw         = (const float*)d_in[8];
    const float* ab         = (const float*)d_in[9];
    const int*   edge_index = (const int*)d_in[10];
    float* out = (float*)d_out;

    cudaFuncSetAttribute(edge_kernel, cudaFuncAttributeMaxDynamicSharedMemorySize, (int)EDGE_SMEM);

    prep_kernel<<<640, 256>>>(fc_w1, fc_w2);
    edge_kernel<<<NTILES, ETHREADS, EDGE_SMEM>>>(node_attr, edge_attr, edge_sh, fc_b1, fc_b2, edge_index);
    node_kernel<<<(N_NODES * 32 + 255) / 256, 256>>>(node_attr, mean_shift, aw, ab, out);
}

// round 13
// speedup vs baseline: 1.1988x; 1.0533x over previous
#include <cuda_runtime.h>
#include <cuda_fp16.h>
#include <cstdint>
#include <cstddef>

#define N_NODES 20000
#define N_EDGES 160000
#define MUL0 32
#define MUL1 16
#define NODE_DIM 80
#define EDGE_FEAT 128
#define HIDDEN 128
#define W_NUMEL 2560
#define MTILE 128
#define NTILES (N_EDGES / MTILE)      // 1250
#define NCHUNK 64
#define NCHUNKS (W_NUMEL / NCHUNK)    // 40
#define ETHREADS 128

#define C0f   0.14433756729740643f
#define C1f   0.21650635094610965f
#define IS3f  0.5773502691896258f
#define IS6f  0.40824829046386296f
#define C0IS3 (C0f * IS3f)
#define C1IS3 (C1f * IS3f)
#define C1IS6 (C1f * IS6f)
#define EPS_LN 1e-5f

// ---------------- device scratch ----------------
__device__ __align__(16) __half g_Bf16[(size_t)W_NUMEL * HIDDEN];  // W2^T fp16 [n][k]
__device__ __align__(16) __half g_W1img[HIDDEN * 136];             // W1^T fp16 image (ROWB layout)
__device__ float g_seg[(size_t)N_NODES * NODE_DIM];
__device__ float g_cnt[N_NODES];

// ---------------- PTX helpers ----------------
__device__ __forceinline__ uint32_t smem_u32(const void* p) {
    uint32_t a;
    asm("{ .reg .u64 t; cvta.to.shared.u64 t, %1; cvt.u32.u64 %0, t; }" : "=r"(a) : "l"(p));
    return a;
}
__device__ __forceinline__ void ldsm_x4(uint32_t* r, uint32_t addr) {
    asm volatile("ldmatrix.sync.aligned.m8n8.x4.shared.b16 {%0,%1,%2,%3}, [%4];"
        : "=r"(r[0]), "=r"(r[1]), "=r"(r[2]), "=r"(r[3]) : "r"(addr));
}
__device__ __forceinline__ void mma_f16(float* c, const uint32_t* a, uint32_t b0, uint32_t b1) {
    asm volatile("mma.sync.aligned.m16n8k16.row.col.f32.f16.f16.f32 "
        "{%0,%1,%2,%3}, {%4,%5,%6,%7}, {%8,%9}, {%0,%1,%2,%3};"
        : "+f"(c[0]), "+f"(c[1]), "+f"(c[2]), "+f"(c[3])
        : "r"(a[0]), "r"(a[1]), "r"(a[2]), "r"(a[3]), "r"(b0), "r"(b1));
}
__device__ __forceinline__ void cp_async16(uint32_t smem_addr, const void* gptr) {
    asm volatile("cp.async.ca.shared.global [%0], [%1], 16;" :: "r"(smem_addr), "l"(gptr));
}
#define CP_COMMIT() asm volatile("cp.async.commit_group;" ::: "memory")
#define CP_WAIT_0() asm volatile("cp.async.wait_group 0;" ::: "memory")
#define CP_WAIT_1() asm volatile("cp.async.wait_group 1;" ::: "memory")

#define ROWB 272

// ---------------- prep: W2^T coalesced transpose + W1 image (zeroing moved to memset) ----------------
__global__ void prep_kernel(const float* __restrict__ fc_w1,
                            const float* __restrict__ fc_w2) {
    __shared__ float tile[64 * 65];
    const int tid = threadIdx.x;
    const int bid = blockIdx.x;

    if (bid < 80) {
        const int kt = bid / 40, nt = bid % 40;
#pragma unroll
        for (int it = 0; it < 16; it++) {
            const int i = tid + it * 256;
            const int r = i >> 6, cc = i & 63;
            tile[r * 65 + cc] = fc_w2[(size_t)(kt * 64 + r) * W_NUMEL + nt * 64 + cc];
        }
        __syncthreads();
#pragma unroll
        for (int it = 0; it < 16; it++) {
            const int i = tid + it * 256;
            const int nn = i >> 6, kk = i & 63;
            g_Bf16[(size_t)(nt * 64 + nn) * HIDDEN + kt * 64 + kk] =
                __float2half_rn(tile[kk * 65 + nn]);
        }
    } else {
        for (int i = tid; i < HIDDEN * HIDDEN; i += 256) {
            const int k = i >> 7, n = i & 127;
            g_W1img[n * 136 + k] = __float2half_rn(fc_w1[i]);
        }
    }
}

// ---------------- fused edge kernel: 128 threads, A-in-regs, 3-stage B ring, fp16 tables ----------------
// Steady SMEM: h[128][272]@0 (34816), B 3x[64][272]@34816 (ends 87040),
//   x0h fp16[128][34]@87040 (8704), x1h fp16[128][50]@95744 (12800),
//   shs f32[128][4]@108544 (2048), srcs@110592 (512) => 111104
// Prologue overlays: attr-hi->A, attr-lo->[34816,69632), W1->[69632,104448)
#define OFF_A    0
#define OFF_B    34816
#define BBUF     17408
#define OFF_W1   69632
#define OFF_X0H  87040
#define OFF_X1H  95744
#define OFF_SH   108544
#define OFF_SRC  110592
#define EDGE_SMEM 111104

__global__ __launch_bounds__(ETHREADS, 2)
void edge_kernel(const float* __restrict__ node_attr,
                 const float* __restrict__ edge_attr,
                 const float* __restrict__ edge_sh,
                 const float* __restrict__ fc_b1,
                 const float* __restrict__ fc_b2,
                 const int*   __restrict__ edge_index) {
    extern __shared__ char smc[];
    const uint32_t smb = smem_u32(smc);
    __half* x0h = (__half*)(smc + OFF_X0H);
    __half* x1h = (__half*)(smc + OFF_X1H);
    float*  shs = (float*)(smc + OFF_SH);
    int*   srcs = (int*)(smc + OFF_SRC);

    const int tid  = threadIdx.x;
    const int w    = tid >> 5;          // warp 0..3 -> rows 32w..32w+31
    const int lane = tid & 31;
    const int e0 = blockIdx.x * MTILE;

    const int q2 = 2 * (lane & 3);
    const int r8 = lane >> 2;

    const uint32_t aRowLoc = (uint32_t)((lane & 7) + 8 * ((lane >> 3) & 1));
    const uint32_t aK = (uint32_t)(16 * ((lane >> 4) & 1));
    const uint32_t bRow = (uint32_t)((lane & 7) + 8 * ((lane >> 4) & 1));
    const uint32_t bK = (uint32_t)(16 * ((lane >> 3) & 1));

    // ======== PROLOGUE: h = relu(edge_attr @ W1 + b1) ========
#pragma unroll
    for (int it = 0; it < 17; it++) {
        const int i = tid + it * ETHREADS;       // W1 image -> OFF_W1
        if (i < 2176)
            cp_async16(smb + OFF_W1 + (uint32_t)i * 16, (const char*)g_W1img + i * 16);
    }
    CP_COMMIT();

    {
        const float4* ga = (const float4*)(edge_attr + (size_t)e0 * EDGE_FEAT);
#pragma unroll 4
        for (int r = 0; r < 32; r++) {
            const int row = 32 * w + r;
            const float4 v = ga[(size_t)row * 32 + lane];
            const __half hx = __float2half_rn(v.x), hy = __float2half_rn(v.y);
            const __half hz = __float2half_rn(v.z), hw = __float2half_rn(v.w);
            const __half lx = __float2half_rn(v.x - __half2float(hx));
            const __half ly = __float2half_rn(v.y - __half2float(hy));
            const __half lz = __float2half_rn(v.z - __half2float(hz));
            const __half lw = __float2half_rn(v.w - __half2float(hw));
            char* dh = smc + OFF_A + row * ROWB + lane * 8;
            char* dl = smc + OFF_B + row * ROWB + lane * 8;
            *(__half2*)(dh)     = __halves2half2(hx, hy);
            *(__half2*)(dh + 4) = __halves2half2(hz, hw);
            *(__half2*)(dl)     = __halves2half2(lx, ly);
            *(__half2*)(dl + 4) = __halves2half2(lz, lw);
        }
    }
    CP_WAIT_0();
    __syncthreads();

    {
        const uint32_t wB = smb + OFF_W1 + bRow * ROWB + bK;
#pragma unroll
        for (int rt = 0; rt < 2; rt++) {
            const uint32_t aHiB = smb + OFF_A + ((uint32_t)(32 * w + 16 * rt) + aRowLoc) * ROWB + aK;
            const uint32_t aLoB = smb + OFF_B + ((uint32_t)(32 * w + 16 * rt) + aRowLoc) * ROWB + aK;
            float c[16][4];
#pragma unroll
            for (int t = 0; t < 16; t++)
#pragma unroll
                for (int i = 0; i < 4; i++) c[t][i] = 0.0f;
#pragma unroll
            for (int ks = 0; ks < 8; ks++) {
                uint32_t ah[4], al[4];
                ldsm_x4(ah, aHiB + ks * 32);
                ldsm_x4(al, aLoB + ks * 32);
#pragma unroll
                for (int tp = 0; tp < 8; tp++) {
                    uint32_t wf[4];
                    ldsm_x4(wf, wB + tp * (16 * ROWB) + ks * 32);
                    mma_f16(c[2 * tp],     ah, wf[0], wf[1]);
                    mma_f16(c[2 * tp],     al, wf[0], wf[1]);
                    mma_f16(c[2 * tp + 1], ah, wf[2], wf[3]);
                    mma_f16(c[2 * tp + 1], al, wf[2], wf[3]);
                }
            }
#pragma unroll
            for (int t = 0; t < 16; t++) {
                const int col = 8 * t + q2;
                const float2 b1v = __ldg((const float2*)(fc_b1 + col));
#pragma unroll
                for (int rr = 0; rr < 2; rr++) {
                    const int mm = 32 * w + 16 * rt + 8 * rr + r8;
                    const float v0 = fmaxf(c[t][2 * rr + 0] + b1v.x, 0.0f);
                    const float v1 = fmaxf(c[t][2 * rr + 1] + b1v.y, 0.0f);
                    *(__half2*)(smc + OFF_A + mm * ROWB + col * 2) =
                        __halves2half2(__float2half_rn(v0), __float2half_rn(v1));
                }
            }
        }
    }
    __syncwarp();

    // A frags -> registers (permanent)
    uint32_t a_[2][8][4];
#pragma unroll
    for (int rt = 0; rt < 2; rt++) {
        const uint32_t base = smb + OFF_A + ((uint32_t)(32 * w + 16 * rt) + aRowLoc) * ROWB + aK;
#pragma unroll
        for (int ks = 0; ks < 8; ks++)
            ldsm_x4(a_[rt][ks], base + ks * 32);
    }
    __syncthreads();      // all warps done reading attr-lo + W1 regions

    // prefetch B0 -> stage0, B1 -> stage1 (separate groups)
#pragma unroll
    for (int it = 0; it < 8; it++) {
        const int i = tid + it * ETHREADS;
        const int row = i >> 4, kc = i & 15;
        cp_async16(smb + OFF_B + row * ROWB + kc * 16,
                   g_Bf16 + (size_t)row * HIDDEN + kc * 8);
    }
    CP_COMMIT();
#pragma unroll
    for (int it = 0; it < 8; it++) {
        const int i = tid + it * ETHREADS;
        const int row = i >> 4, kc = i & 15;
        cp_async16(smb + OFF_B + BBUF + row * ROWB + kc * 16,
                   g_Bf16 + (size_t)(NCHUNK + row) * HIDDEN + kc * 8);
    }
    CP_COMMIT();

    // gather per-edge vectors (fp16 tables)
    {
        const int eg  = e0 + tid;
        const int src = edge_index[eg];
        const int dst = edge_index[N_EDGES + eg];
        srcs[tid] = src;
        atomicAdd(&g_cnt[src], 1.0f);
        const float4* na = (const float4*)(node_attr + (size_t)dst * NODE_DIM);
#pragma unroll
        for (int q = 0; q < 8; q++) {
            const float4 v = na[q];
            __half2* p = (__half2*)(x0h + tid * 34 + 4 * q);
            p[0] = __floats2half2_rn(v.x, v.y);
            p[1] = __floats2half2_rn(v.z, v.w);
        }
#pragma unroll
        for (int q = 0; q < 12; q++) {
            const float4 v = na[8 + q];
            __half2* p = (__half2*)(x1h + tid * 50 + 4 * q);
            p[0] = __floats2half2_rn(v.x, v.y);
            p[1] = __floats2half2_rn(v.z, v.w);
        }
        const float4 sh4 = *(const float4*)(edge_sh + (size_t)eg * 4);
        shs[tid * 4 + 0] = sh4.x;
        shs[tid * 4 + 1] = sh4.y;
        shs[tid * 4 + 2] = sh4.z;
        shs[tid * 4 + 3] = sh4.w;
    }

    // ======== STEADY STATE ========
    const uint32_t bRowOff = bRow * ROWB + bK;
    int mmr[4];
#pragma unroll
    for (int r = 0; r < 4; r++) mmr[r] = 32 * w + 16 * (r >> 1) + 8 * (r & 1) + r8;

    float sh0r[4], sh1r[4][3];
    bool shLoaded = false;

#define CHUNK_TOP(j) \
    if ((j) + 1 < NCHUNKS) { CP_WAIT_1(); } else { CP_WAIT_0(); } \
    __syncthreads(); \
    if ((j) + 2 < NCHUNKS) { \
        const uint32_t sb = smb + OFF_B + (uint32_t)((((j) + 2) % 3) * BBUF); \
        const __half* gp0 = g_Bf16 + (size_t)((j) + 2) * NCHUNK * HIDDEN; \
        _Pragma("unroll") \
        for (int it = 0; it < 8; it++) { \
            const int i = tid + it * ETHREADS; \
            const int row = i >> 4, kc = i & 15; \
            cp_async16(sb + row * ROWB + kc * 16, gp0 + (size_t)row * HIDDEN + kc * 8); \
        } \
        CP_COMMIT(); \
    }

#define LOAD_SH() \
    if (!shLoaded) { \
        _Pragma("unroll") for (int r = 0; r < 4; r++) { \
            sh0r[r] = shs[mmr[r] * 4 + 0]; \
            sh1r[r][0] = shs[mmr[r] * 4 + 1]; \
            sh1r[r][1] = shs[mmr[r] * 4 + 2]; \
            sh1r[r][2] = shs[mmr[r] * 4 + 3]; \
        } \
        shLoaded = true; \
    }

#define CHUNK_MMA(j) \
    float c2[2][8][4]; \
    { \
        _Pragma("unroll") for (int rt = 0; rt < 2; rt++) \
        _Pragma("unroll") for (int t = 0; t < 8; t++) \
        _Pragma("unroll") for (int i = 0; i < 4; i++) c2[rt][t][i] = 0.0f; \
        const uint32_t bb = smb + OFF_B + (uint32_t)(((j) % 3) * BBUF) + bRowOff; \
        _Pragma("unroll") for (int ks = 0; ks < 8; ks++) { \
            _Pragma("unroll") for (int tp = 0; tp < 4; tp++) { \
                uint32_t bf[4]; \
                ldsm_x4(bf, bb + tp * (16 * ROWB) + ks * 32); \
                mma_f16(c2[0][2 * tp],     a_[0][ks], bf[0], bf[1]); \
                mma_f16(c2[0][2 * tp + 1], a_[0][ks], bf[2], bf[3]); \
                mma_f16(c2[1][2 * tp],     a_[1][ks], bf[0], bf[1]); \
                mma_f16(c2[1][2 * tp + 1], a_[1][ks], bf[2], bf[3]); \
            } \
        } \
    }

    // ============ phase 1: j 0..23 (block1/block2 -> accO) ============
    {
        float accO[4][8];
#pragma unroll
        for (int r = 0; r < 4; r++)
#pragma unroll
            for (int i = 0; i < 8; i++) accO[r][i] = 0.0f;

        for (int j = 0; j < 24; j++) {
            CHUNK_TOP(j);
            LOAD_SH();
            CHUNK_MMA(j);
#pragma unroll
            for (int gi = 0; gi < 2; gi++) {
                const int g = 2 * j + gi;
                float s[4];
                if (g < 32) {
#pragma unroll
                    for (int r = 0; r < 4; r++)
                        s[r] = C0f * sh0r[r] * __half2float(x0h[mmr[r] * 34 + g]);
                } else {
                    const int u = g - 32;
#pragma unroll
                    for (int r = 0; r < 4; r++)
                        s[r] = C0IS3 * (__half2float(x1h[mmr[r] * 50 + 3 * u])     * sh1r[r][0]
                                      + __half2float(x1h[mmr[r] * 50 + 3 * u + 1]) * sh1r[r][1]
                                      + __half2float(x1h[mmr[r] * 50 + 3 * u + 2]) * sh1r[r][2]);
                }
#pragma unroll
                for (int tt = 0; tt < 4; tt++) {
                    const float2 bv = __ldg((const float2*)(fc_b2 + 32 * g + 8 * tt + q2));
#pragma unroll
                    for (int rt = 0; rt < 2; rt++)
#pragma unroll
                        for (int rr = 0; rr < 2; rr++) {
                            const int r = 2 * rt + rr;
                            float* cc = c2[rt][4 * gi + tt];
                            accO[r][2 * tt]     += s[r] * (cc[2 * rr]     + bv.x);
                            accO[r][2 * tt + 1] += s[r] * (cc[2 * rr + 1] + bv.y);
                        }
                }
            }
        }
#pragma unroll
        for (int r = 0; r < 4; r++) {
            float* segp = g_seg + (size_t)srcs[mmr[r]] * NODE_DIM;
#pragma unroll
            for (int tt = 0; tt < 4; tt++)
#pragma unroll
                for (int b = 0; b < 2; b++)
                    atomicAdd(segp + 8 * tt + q2 + b, accO[r][2 * tt + b]);
        }
    }

    // ============ phase 2: j 24..31 (block3 -> t3) ============
    {
        float accT3[4][4];
#pragma unroll
        for (int r = 0; r < 4; r++)
#pragma unroll
            for (int i = 0; i < 4; i++) accT3[r][i] = 0.0f;

        for (int j = 24; j < 32; j++) {
            CHUNK_TOP(j);
            CHUNK_MMA(j);
#pragma unroll
            for (int gi = 0; gi < 2; gi++) {
                const int g = 2 * j + gi;
                const int u0 = 2 * (g - 48);
                float s[4][2];
#pragma unroll
                for (int r = 0; r < 4; r++) {
                    s[r][0] = C1IS3 * __half2float(x0h[mmr[r] * 34 + u0]);
                    s[r][1] = C1IS3 * __half2float(x0h[mmr[r] * 34 + u0 + 1]);
                }
#pragma unroll
                for (int tt = 0; tt < 4; tt++) {
                    const int us = tt >> 1;
                    const int sl = 2 * (tt & 1);
                    const float2 bv = __ldg((const float2*)(fc_b2 + 32 * g + 8 * tt + q2));
#pragma unroll
                    for (int rt = 0; rt < 2; rt++)
#pragma unroll
                        for (int rr = 0; rr < 2; rr++) {
                            const int r = 2 * rt + rr;
                            float* cc = c2[rt][4 * gi + tt];
                            accT3[r][sl]     += s[r][us] * (cc[2 * rr]     + bv.x);
                            accT3[r][sl + 1] += s[r][us] * (cc[2 * rr + 1] + bv.y);
                        }
                }
            }
        }
#pragma unroll
        for (int r = 0; r < 4; r++) {
            float* segp = g_seg + (size_t)srcs[mmr[r]] * NODE_DIM;
#pragma unroll
            for (int ws = 0; ws < 2; ws++)
#pragma unroll
                for (int b = 0; b < 2; b++) {
                    const int wc = 8 * ws + q2 + b;
                    const float t3 = accT3[r][2 * ws + b];
                    atomicAdd(segp + 32 + 3 * wc + 0, sh1r[r][0] * t3);
                    atomicAdd(segp + 32 + 3 * wc + 1, sh1r[r][1] * t3);
                    atomicAdd(segp + 32 + 3 * wc + 2, sh1r[r][2] * t3);
                }
        }
    }

    // ============ phase 3: j 32..39 (block4/5 -> V) ============
    {
        float accV[4][4][3];
#pragma unroll
        for (int r = 0; r < 4; r++)
#pragma unroll
            for (int i = 0; i < 4; i++)
#pragma unroll
                for (int k = 0; k < 3; k++) accV[r][i][k] = 0.0f;

        for (int j = 32; j < 40; j++) {
            CHUNK_TOP(j);
            CHUNK_MMA(j);
#pragma unroll
            for (int gi = 0; gi < 2; gi++) {
                const int g = 2 * j + gi;
                const bool is5 = (g >= 72);
                const int u0 = is5 ? 2 * (g - 72) : 2 * (g - 64);
                float av[4][2][3];
#pragma unroll
                for (int r = 0; r < 4; r++) {
#pragma unroll
                    for (int us = 0; us < 2; us++) {
                        const int u = u0 + us;
                        const float xx = __half2float(x1h[mmr[r] * 50 + 3 * u + 0]);
                        const float xy = __half2float(x1h[mmr[r] * 50 + 3 * u + 1]);
                        const float xz = __half2float(x1h[mmr[r] * 50 + 3 * u + 2]);
                        if (!is5) {
                            const float kb = C1IS3 * sh0r[r];
                            av[r][us][0] = kb * xx;
                            av[r][us][1] = kb * xy;
                            av[r][us][2] = kb * xz;
                        } else {
                            av[r][us][0] = C1IS6 * (xy * sh1r[r][2] - xz * sh1r[r][1]);
                            av[r][us][1] = C1IS6 * (xz * sh1r[r][0] - xx * sh1r[r][2]);
                            av[r][us][2] = C1IS6 * (xx * sh1r[r][1] - xy * sh1r[r][0]);
                        }
                    }
                }
#pragma unroll
                for (int tt = 0; tt < 4; tt++) {
                    const int us = tt >> 1;
                    const int sl = 2 * (tt & 1);
                    const float2 bv = __ldg((const float2*)(fc_b2 + 32 * g + 8 * tt + q2));
#pragma unroll
                    for (int rt = 0; rt < 2; rt++)
#pragma unroll
                        for (int rr = 0; rr < 2; rr++) {
                            const int r = 2 * rt + rr;
                            float* cc = c2[rt][4 * gi + tt];
                            const float D0 = cc[2 * rr] + bv.x;
                            const float D1 = cc[2 * rr + 1] + bv.y;
#pragma unroll
                            for (int k = 0; k < 3; k++) {
                                accV[r][sl][k]     += av[r][us][k] * D0;
                                accV[r][sl + 1][k] += av[r][us][k] * D1;
                            }
                        }
                }
            }
        }
#pragma unroll
        for (int r = 0; r < 4; r++) {
            float* segp = g_seg + (size_t)srcs[mmr[r]] * NODE_DIM;
#pragma unroll
            for (int ws = 0; ws < 2; ws++)
#pragma unroll
                for (int b = 0; b < 2; b++) {
                    const int wc = 8 * ws + q2 + b;
#pragma unroll
                    for (int k = 0; k < 3; k++)
                        atomicAdd(segp + 32 + 3 * wc + k, accV[r][2 * ws + b][k]);
                }
        }
    }
}

// ---------------- node epilogue ----------------
__global__ void node_kernel(const float* __restrict__ node_attr,
                            const float* __restrict__ mean_shift,
                            const float* __restrict__ aw,
                            const float* __restrict__ ab,
                            float* __restrict__ out) {
    const int warp = (blockIdx.x * blockDim.x + threadIdx.x) >> 5;
    const int lane = threadIdx.x & 31;
    if (warp >= N_NODES) return;
    const unsigned full = 0xFFFFFFFFu;

    const float inv = 1.0f / fmaxf(g_cnt[warp], 1.0f);
    const float* seg = g_seg + (size_t)warp * NODE_DIM;
    const float* na  = node_attr + (size_t)warp * NODE_DIM;

    float o0 = seg[lane] * inv + na[lane];
    float mval = o0;
#pragma unroll
    for (int off = 16; off; off >>= 1) mval += __shfl_xor_sync(full, mval, off);
    mval *= (1.0f / 32.0f);
    const float f0 = o0 - mval * mean_shift[lane];
    float s = f0 * f0;
#pragma unroll
    for (int off = 16; off; off >>= 1) s += __shfl_xor_sync(full, s, off);
    const float sc0 = rsqrtf(s * (1.0f / 32.0f) + EPS_LN) * aw[lane];
    out[(size_t)warp * NODE_DIM + lane] = f0 * sc0 + ab[lane];

    float vx = 0.0f, vy = 0.0f, vz = 0.0f, msv = 0.0f;
    if (lane < 16) {
        vx = seg[32 + 3 * lane + 0] * inv + na[32 + 3 * lane + 0];
        vy = seg[32 + 3 * lane + 1] * inv + na[32 + 3 * lane + 1];
        vz = seg[32 + 3 * lane + 2] * inv + na[32 + 3 * lane + 2];
        msv = mean_shift[32 + lane];
    }
    float mx = vx, my = vy, mz = vz;
#pragma unroll
    for (int off = 16; off; off >>= 1) {
        mx += __shfl_xor_sync(full, mx, off);
        my += __shfl_xor_sync(full, my, off);
        mz += __shfl_xor_sync(full, mz, off);
    }
    mx *= (1.0f / 16.0f); my *= (1.0f / 16.0f); mz *= (1.0f / 16.0f);
    const float fx = vx - mx * msv;
    const float fy = vy - my * msv;
    const float fz = vz - mz * msv;
    float sq = (lane < 16) ? (fx * fx + fy * fy + fz * fz) : 0.0f;
#pragma unroll
    for (int off = 16; off; off >>= 1) sq += __shfl_xor_sync(full, sq, off);
    if (lane < 16) {
        const float sc1 = rsqrtf(sq * (1.0f / 48.0f) + EPS_LN) * aw[32 + lane];
        out[(size_t)warp * NODE_DIM + 32 + 3 * lane + 0] = fx * sc1;
        out[(size_t)warp * NODE_DIM + 32 + 3 * lane + 1] = fy * sc1;
        out[(size_t)warp * NODE_DIM + 32 + 3 * lane + 2] = fz * sc1;
    }
}

// ---------------- launch ----------------
extern "C" void kernel_launch(void* const* d_in, const int* in_sizes, int n_in,
                              void* d_out, int out_size) {
    const float* node_attr  = (const float*)d_in[0];
    const float* edge_attr  = (const float*)d_in[1];
    const float* edge_sh    = (const float*)d_in[2];
    const float* fc_w1      = (const float*)d_in[3];
    const float* fc_b1      = (const float*)d_in[4];
    const float* fc_w2      = (const float*)d_in[5];
    const float* fc_b2      = (const float*)d_in[6];
    const float* mean_shift = (const float*)d_in[7];
    const float* aw         = (const float*)d_in[8];
    const float* ab         = (const float*)d_in[9];
    const int*   edge_index = (const int*)d_in[10];
    float* out = (float*)d_out;

    cudaFuncSetAttribute(edge_kernel, cudaFuncAttributeMaxDynamicSharedMemorySize, (int)EDGE_SMEM);

    void* seg_ptr = nullptr;
    void* cnt_ptr = nullptr;
    cudaGetSymbolAddress(&seg_ptr, g_seg);
    cudaGetSymbolAddress(&cnt_ptr, g_cnt);
    cudaMemsetAsync(seg_ptr, 0, sizeof(float) * (size_t)N_NODES * NODE_DIM);
    cudaMemsetAsync(cnt_ptr, 0, sizeof(float) * N_NODES);

    prep_kernel<<<81, 256>>>(fc_w1, fc_w2);
    edge_kernel<<<NTILES, ETHREADS, EDGE_SMEM>>>(node_attr, edge_attr, edge_sh, fc_b1, fc_b2, edge_index);
    node_kernel<<<(N_NODES * 32 + 255) / 256, 256>>>(node_attr, mean_shift, aw, ab, out);
}

// round 14
// speedup vs baseline: 1.2484x; 1.0414x over previous
#include <cuda_runtime.h>
#include <cuda_fp16.h>
#include <cstdint>
#include <cstddef>

#define N_NODES 20000
#define N_EDGES 160000
#define MUL0 32
#define MUL1 16
#define NODE_DIM 80
#define EDGE_FEAT 128
#define HIDDEN 128
#define W_NUMEL 2560
#define MTILE 128
#define NTILES (N_EDGES / MTILE)      // 1250
#define NCHUNK 64
#define NCHUNKS (W_NUMEL / NCHUNK)    // 40
#define ETHREADS 128

#define C0f   0.14433756729740643f
#define C1f   0.21650635094610965f
#define IS3f  0.5773502691896258f
#define IS6f  0.40824829046386296f
#define C0IS3 (C0f * IS3f)
#define C1IS3 (C1f * IS3f)
#define C1IS6 (C1f * IS6f)
#define EPS_LN 1e-5f

// ---------------- device scratch ----------------
__device__ __align__(16) __half g_Bf16[(size_t)W_NUMEL * HIDDEN];  // W2^T fp16 [n][k]
__device__ __align__(16) __half g_W1img[HIDDEN * 136];             // W1^T fp16 image (ROWB layout)
__device__ float g_seg[(size_t)N_NODES * NODE_DIM];
__device__ float g_cnt[N_NODES];

// ---------------- PTX helpers ----------------
__device__ __forceinline__ uint32_t smem_u32(const void* p) {
    uint32_t a;
    asm("{ .reg .u64 t; cvta.to.shared.u64 t, %1; cvt.u32.u64 %0, t; }" : "=r"(a) : "l"(p));
    return a;
}
__device__ __forceinline__ void ldsm_x4(uint32_t* r, uint32_t addr) {
    asm volatile("ldmatrix.sync.aligned.m8n8.x4.shared.b16 {%0,%1,%2,%3}, [%4];"
        : "=r"(r[0]), "=r"(r[1]), "=r"(r[2]), "=r"(r[3]) : "r"(addr));
}
__device__ __forceinline__ void mma_f16(float* c, const uint32_t* a, uint32_t b0, uint32_t b1) {
    asm volatile("mma.sync.aligned.m16n8k16.row.col.f32.f16.f16.f32 "
        "{%0,%1,%2,%3}, {%4,%5,%6,%7}, {%8,%9}, {%0,%1,%2,%3};"
        : "+f"(c[0]), "+f"(c[1]), "+f"(c[2]), "+f"(c[3])
        : "r"(a[0]), "r"(a[1]), "r"(a[2]), "r"(a[3]), "r"(b0), "r"(b1));
}
__device__ __forceinline__ void cp_async16(uint32_t smem_addr, const void* gptr) {
    asm volatile("cp.async.ca.shared.global [%0], [%1], 16;" :: "r"(smem_addr), "l"(gptr));
}
#define CP_COMMIT() asm volatile("cp.async.commit_group;" ::: "memory")
#define CP_WAIT_0() asm volatile("cp.async.wait_group 0;" ::: "memory")
#define CP_WAIT_1() asm volatile("cp.async.wait_group 1;" ::: "memory")

#define ROWB 272

// ---------------- prep: W2^T transpose (320 blocks of 16x64 tiles) + W1 image ----------------
__global__ void prep_kernel(const float* __restrict__ fc_w1,
                            const float* __restrict__ fc_w2) {
    __shared__ float tile[16 * 65];
    const int tid = threadIdx.x;
    const int bid = blockIdx.x;

    if (bid < 320) {
        const int kt = bid / 40;      // 0..7 -> k rows 16kt..16kt+15
        const int nt = bid % 40;      // n cols 64nt..64nt+63
#pragma unroll
        for (int it = 0; it < 4; it++) {
            const int i = tid + it * 256;       // 0..1023
            const int r = i >> 6, cc = i & 63;
            tile[r * 65 + cc] = fc_w2[(size_t)(kt * 16 + r) * W_NUMEL + nt * 64 + cc];
        }
        __syncthreads();
#pragma unroll
        for (int it = 0; it < 4; it++) {
            const int i = tid + it * 256;
            const int nn = i >> 4, kk = i & 15;   // 64 n-rows x 16 k
            g_Bf16[(size_t)(nt * 64 + nn) * HIDDEN + kt * 16 + kk] =
                __float2half_rn(tile[kk * 65 + nn]);
        }
    } else {
        for (int i = tid; i < HIDDEN * HIDDEN; i += 256) {
            const int k = i >> 7, n = i & 127;
            g_W1img[n * 136 + k] = __float2half_rn(fc_w1[i]);
        }
    }
}

// ---------------- fused edge kernel: 128 threads, A-in-regs, 3-stage B ring, b2 in SMEM ----------------
// Steady SMEM: h[128][272]@0 (34816), B 3x[64][272]@34816 (ends 87040),
//   x0h fp16[128][34]@87040 (8704), x1h fp16[128][50]@95744 (12800),
//   shs f32[128][4]@108544 (2048), srcs@110592 (512) => 111104
// Prologue overlays: attr-hi->A, attr-lo->[34816,69632), W1->[69632,104448);
// after prologue, b2s f32[2560] lives at OFF_B2=69632 (inside dead W1 region).
#define OFF_A    0
#define OFF_B    34816
#define BBUF     17408
#define OFF_W1   69632
#define OFF_B2   69632
#define OFF_X0H  87040
#define OFF_X1H  95744
#define OFF_SH   108544
#define OFF_SRC  110592
#define EDGE_SMEM 111104

__global__ __launch_bounds__(ETHREADS, 2)
void edge_kernel(const float* __restrict__ node_attr,
                 const float* __restrict__ edge_attr,
                 const float* __restrict__ edge_sh,
                 const float* __restrict__ fc_b1,
                 const float* __restrict__ fc_b2,
                 const int*   __restrict__ edge_index) {
    extern __shared__ char smc[];
    const uint32_t smb = smem_u32(smc);
    __half* x0h = (__half*)(smc + OFF_X0H);
    __half* x1h = (__half*)(smc + OFF_X1H);
    float*  shs = (float*)(smc + OFF_SH);
    int*   srcs = (int*)(smc + OFF_SRC);
    const float* b2s = (const float*)(smc + OFF_B2);

    const int tid  = threadIdx.x;
    const int w    = tid >> 5;          // warp 0..3 -> rows 32w..32w+31
    const int lane = tid & 31;
    const int e0 = blockIdx.x * MTILE;

    const int q2 = 2 * (lane & 3);
    const int r8 = lane >> 2;

    const uint32_t aRowLoc = (uint32_t)((lane & 7) + 8 * ((lane >> 3) & 1));
    const uint32_t aK = (uint32_t)(16 * ((lane >> 4) & 1));
    const uint32_t bRow = (uint32_t)((lane & 7) + 8 * ((lane >> 4) & 1));
    const uint32_t bK = (uint32_t)(16 * ((lane >> 3) & 1));

    // ======== PROLOGUE: h = relu(edge_attr @ W1 + b1) ========
#pragma unroll
    for (int it = 0; it < 17; it++) {
        const int i = tid + it * ETHREADS;       // W1 image -> OFF_W1
        if (i < 2176)
            cp_async16(smb + OFF_W1 + (uint32_t)i * 16, (const char*)g_W1img + i * 16);
    }
    CP_COMMIT();

    {
        const float4* ga = (const float4*)(edge_attr + (size_t)e0 * EDGE_FEAT);
#pragma unroll 4
        for (int r = 0; r < 32; r++) {
            const int row = 32 * w + r;
            const float4 v = ga[(size_t)row * 32 + lane];
            const __half hx = __float2half_rn(v.x), hy = __float2half_rn(v.y);
            const __half hz = __float2half_rn(v.z), hw = __float2half_rn(v.w);
            const __half lx = __float2half_rn(v.x - __half2float(hx));
            const __half ly = __float2half_rn(v.y - __half2float(hy));
            const __half lz = __float2half_rn(v.z - __half2float(hz));
            const __half lw = __float2half_rn(v.w - __half2float(hw));
            char* dh = smc + OFF_A + row * ROWB + lane * 8;
            char* dl = smc + OFF_B + row * ROWB + lane * 8;
            *(__half2*)(dh)     = __halves2half2(hx, hy);
            *(__half2*)(dh + 4) = __halves2half2(hz, hw);
            *(__half2*)(dl)     = __halves2half2(lx, ly);
            *(__half2*)(dl + 4) = __halves2half2(lz, lw);
        }
    }
    CP_WAIT_0();
    __syncthreads();

    {
        const uint32_t wB = smb + OFF_W1 + bRow * ROWB + bK;
#pragma unroll
        for (int rt = 0; rt < 2; rt++) {
            const uint32_t aHiB = smb + OFF_A + ((uint32_t)(32 * w + 16 * rt) + aRowLoc) * ROWB + aK;
            const uint32_t aLoB = smb + OFF_B + ((uint32_t)(32 * w + 16 * rt) + aRowLoc) * ROWB + aK;
            float c[16][4];
#pragma unroll
            for (int t = 0; t < 16; t++)
#pragma unroll
                for (int i = 0; i < 4; i++) c[t][i] = 0.0f;
#pragma unroll
            for (int ks = 0; ks < 8; ks++) {
                uint32_t ah[4], al[4];
                ldsm_x4(ah, aHiB + ks * 32);
                ldsm_x4(al, aLoB + ks * 32);
#pragma unroll
                for (int tp = 0; tp < 8; tp++) {
                    uint32_t wf[4];
                    ldsm_x4(wf, wB + tp * (16 * ROWB) + ks * 32);
                    mma_f16(c[2 * tp],     ah, wf[0], wf[1]);
                    mma_f16(c[2 * tp],     al, wf[0], wf[1]);
                    mma_f16(c[2 * tp + 1], ah, wf[2], wf[3]);
                    mma_f16(c[2 * tp + 1], al, wf[2], wf[3]);
                }
            }
#pragma unroll
            for (int t = 0; t < 16; t++) {
                const int col = 8 * t + q2;
                const float2 b1v = __ldg((const float2*)(fc_b1 + col));
#pragma unroll
                for (int rr = 0; rr < 2; rr++) {
                    const int mm = 32 * w + 16 * rt + 8 * rr + r8;
                    const float v0 = fmaxf(c[t][2 * rr + 0] + b1v.x, 0.0f);
                    const float v1 = fmaxf(c[t][2 * rr + 1] + b1v.y, 0.0f);
                    *(__half2*)(smc + OFF_A + mm * ROWB + col * 2) =
                        __halves2half2(__float2half_rn(v0), __float2half_rn(v1));
                }
            }
        }
    }
    __syncwarp();

    // A frags -> registers (permanent)
    uint32_t a_[2][8][4];
#pragma unroll
    for (int rt = 0; rt < 2; rt++) {
        const uint32_t base = smb + OFF_A + ((uint32_t)(32 * w + 16 * rt) + aRowLoc) * ROWB + aK;
#pragma unroll
        for (int ks = 0; ks < 8; ks++)
            ldsm_x4(a_[rt][ks], base + ks * 32);
    }
    __syncthreads();      // all warps done reading attr-lo + W1 regions

    // prefetch B0 -> stage0 (+ b2 table into dead W1 region), then B1 -> stage1
#pragma unroll
    for (int it = 0; it < 8; it++) {
        const int i = tid + it * ETHREADS;
        const int row = i >> 4, kc = i & 15;
        cp_async16(smb + OFF_B + row * ROWB + kc * 16,
                   g_Bf16 + (size_t)row * HIDDEN + kc * 8);
    }
#pragma unroll
    for (int it = 0; it < 5; it++) {
        const int i = tid + it * ETHREADS;       // 0..639 x 16B = 10240B
        cp_async16(smb + OFF_B2 + (uint32_t)i * 16, fc_b2 + i * 4);
    }
    CP_COMMIT();
#pragma unroll
    for (int it = 0; it < 8; it++) {
        const int i = tid + it * ETHREADS;
        const int row = i >> 4, kc = i & 15;
        cp_async16(smb + OFF_B + BBUF + row * ROWB + kc * 16,
                   g_Bf16 + (size_t)(NCHUNK + row) * HIDDEN + kc * 8);
    }
    CP_COMMIT();

    // gather per-edge vectors (fp16 tables)
    {
        const int eg  = e0 + tid;
        const int src = edge_index[eg];
        const int dst = edge_index[N_EDGES + eg];
        srcs[tid] = src;
        atomicAdd(&g_cnt[src], 1.0f);
        const float4* na = (const float4*)(node_attr + (size_t)dst * NODE_DIM);
#pragma unroll
        for (int q = 0; q < 8; q++) {
            const float4 v = na[q];
            __half2* p = (__half2*)(x0h + tid * 34 + 4 * q);
            p[0] = __floats2half2_rn(v.x, v.y);
            p[1] = __floats2half2_rn(v.z, v.w);
        }
#pragma unroll
        for (int q = 0; q < 12; q++) {
            const float4 v = na[8 + q];
            __half2* p = (__half2*)(x1h + tid * 50 + 4 * q);
            p[0] = __floats2half2_rn(v.x, v.y);
            p[1] = __floats2half2_rn(v.z, v.w);
        }
        const float4 sh4 = *(const float4*)(edge_sh + (size_t)eg * 4);
        shs[tid * 4 + 0] = sh4.x;
        shs[tid * 4 + 1] = sh4.y;
        shs[tid * 4 + 2] = sh4.z;
        shs[tid * 4 + 3] = sh4.w;
    }

    // ======== STEADY STATE ========
    const uint32_t bRowOff = bRow * ROWB + bK;
    int mmr[4];
#pragma unroll
    for (int r = 0; r < 4; r++) mmr[r] = 32 * w + 16 * (r >> 1) + 8 * (r & 1) + r8;

    float sh0r[4], sh1r[4][3];
    bool shLoaded = false;

#define CHUNK_TOP(j) \
    if ((j) + 1 < NCHUNKS) { CP_WAIT_1(); } else { CP_WAIT_0(); } \
    __syncthreads(); \
    if ((j) + 2 < NCHUNKS) { \
        const uint32_t sb = smb + OFF_B + (uint32_t)((((j) + 2) % 3) * BBUF); \
        const __half* gp0 = g_Bf16 + (size_t)((j) + 2) * NCHUNK * HIDDEN; \
        _Pragma("unroll") \
        for (int it = 0; it < 8; it++) { \
            const int i = tid + it * ETHREADS; \
            const int row = i >> 4, kc = i & 15; \
            cp_async16(sb + row * ROWB + kc * 16, gp0 + (size_t)row * HIDDEN + kc * 8); \
        } \
        CP_COMMIT(); \
    }

#define LOAD_SH() \
    if (!shLoaded) { \
        _Pragma("unroll") for (int r = 0; r < 4; r++) { \
            sh0r[r] = shs[mmr[r] * 4 + 0]; \
            sh1r[r][0] = shs[mmr[r] * 4 + 1]; \
            sh1r[r][1] = shs[mmr[r] * 4 + 2]; \
            sh1r[r][2] = shs[mmr[r] * 4 + 3]; \
        } \
        shLoaded = true; \
    }

#define CHUNK_MMA(j) \
    float c2[2][8][4]; \
    { \
        _Pragma("unroll") for (int rt = 0; rt < 2; rt++) \
        _Pragma("unroll") for (int t = 0; t < 8; t++) \
        _Pragma("unroll") for (int i = 0; i < 4; i++) c2[rt][t][i] = 0.0f; \
        const uint32_t bb = smb + OFF_B + (uint32_t)(((j) % 3) * BBUF) + bRowOff; \
        _Pragma("unroll") for (int ks = 0; ks < 8; ks++) { \
            _Pragma("unroll") for (int tp = 0; tp < 4; tp++) { \
                uint32_t bf[4]; \
                ldsm_x4(bf, bb + tp * (16 * ROWB) + ks * 32); \
                mma_f16(c2[0][2 * tp],     a_[0][ks], bf[0], bf[1]); \
                mma_f16(c2[0][2 * tp + 1], a_[0][ks], bf[2], bf[3]); \
                mma_f16(c2[1][2 * tp],     a_[1][ks], bf[0], bf[1]); \
                mma_f16(c2[1][2 * tp + 1], a_[1][ks], bf[2], bf[3]); \
            } \
        } \
    }

    // ============ phase 1: j 0..23 (block1/block2 -> accO) ============
    {
        float accO[4][8];
#pragma unroll
        for (int r = 0; r < 4; r++)
#pragma unroll
            for (int i = 0; i < 8; i++) accO[r][i] = 0.0f;

        for (int j = 0; j < 24; j++) {
            CHUNK_TOP(j);
            LOAD_SH();
            CHUNK_MMA(j);
#pragma unroll
            for (int gi = 0; gi < 2; gi++) {
                const int g = 2 * j + gi;
                float s[4];
                if (g < 32) {
#pragma unroll
                    for (int r = 0; r < 4; r++)
                        s[r] = C0f * sh0r[r] * __half2float(x0h[mmr[r] * 34 + g]);
                } else {
                    const int u = g - 32;
#pragma unroll
                    for (int r = 0; r < 4; r++)
                        s[r] = C0IS3 * (__half2float(x1h[mmr[r] * 50 + 3 * u])     * sh1r[r][0]
                                      + __half2float(x1h[mmr[r] * 50 + 3 * u + 1]) * sh1r[r][1]
                                      + __half2float(x1h[mmr[r] * 50 + 3 * u + 2]) * sh1r[r][2]);
                }
#pragma unroll
                for (int tt = 0; tt < 4; tt++) {
                    const float2 bv = *(const float2*)(b2s + 32 * g + 8 * tt + q2);
#pragma unroll
                    for (int rt = 0; rt < 2; rt++)
#pragma unroll
                        for (int rr = 0; rr < 2; rr++) {
                            const int r = 2 * rt + rr;
                            float* cc = c2[rt][4 * gi + tt];
                            accO[r][2 * tt]     += s[r] * (cc[2 * rr]     + bv.x);
                            accO[r][2 * tt + 1] += s[r] * (cc[2 * rr + 1] + bv.y);
                        }
                }
            }
        }
#pragma unroll
        for (int r = 0; r < 4; r++) {
            float* segp = g_seg + (size_t)srcs[mmr[r]] * NODE_DIM;
#pragma unroll
            for (int tt = 0; tt < 4; tt++)
#pragma unroll
                for (int b = 0; b < 2; b++)
                    atomicAdd(segp + 8 * tt + q2 + b, accO[r][2 * tt + b]);
        }
    }

    // ============ phase 2: j 24..31 (block3 -> t3) ============
    {
        float accT3[4][4];
#pragma unroll
        for (int r = 0; r < 4; r++)
#pragma unroll
            for (int i = 0; i < 4; i++) accT3[r][i] = 0.0f;

        for (int j = 24; j < 32; j++) {
            CHUNK_TOP(j);
            CHUNK_MMA(j);
#pragma unroll
            for (int gi = 0; gi < 2; gi++) {
                const int g = 2 * j + gi;
                const int u0 = 2 * (g - 48);
                float s[4][2];
#pragma unroll
                for (int r = 0; r < 4; r++) {
                    s[r][0] = C1IS3 * __half2float(x0h[mmr[r] * 34 + u0]);
                    s[r][1] = C1IS3 * __half2float(x0h[mmr[r] * 34 + u0 + 1]);
                }
#pragma unroll
                for (int tt = 0; tt < 4; tt++) {
                    const int us = tt >> 1;
                    const int sl = 2 * (tt & 1);
                    const float2 bv = *(const float2*)(b2s + 32 * g + 8 * tt + q2);
#pragma unroll
                    for (int rt = 0; rt < 2; rt++)
#pragma unroll
                        for (int rr = 0; rr < 2; rr++) {
                            const int r = 2 * rt + rr;
                            float* cc = c2[rt][4 * gi + tt];
                            accT3[r][sl]     += s[r][us] * (cc[2 * rr]     + bv.x);
                            accT3[r][sl + 1] += s[r][us] * (cc[2 * rr + 1] + bv.y);
                        }
                }
            }
        }
#pragma unroll
        for (int r = 0; r < 4; r++) {
            float* segp = g_seg + (size_t)srcs[mmr[r]] * NODE_DIM;
#pragma unroll
            for (int ws = 0; ws < 2; ws++)
#pragma unroll
                for (int b = 0; b < 2; b++) {
                    const int wc = 8 * ws + q2 + b;
                    const float t3 = accT3[r][2 * ws + b];
                    atomicAdd(segp + 32 + 3 * wc + 0, sh1r[r][0] * t3);
                    atomicAdd(segp + 32 + 3 * wc + 1, sh1r[r][1] * t3);
                    atomicAdd(segp + 32 + 3 * wc + 2, sh1r[r][2] * t3);
                }
        }
    }

    // ============ phase 3: j 32..39 (block4/5 -> V) ============
    {
        float accV[4][4][3];
#pragma unroll
        for (int r = 0; r < 4; r++)
#pragma unroll
            for (int i = 0; i < 4; i++)
#pragma unroll
                for (int k = 0; k < 3; k++) accV[r][i][k] = 0.0f;

        for (int j = 32; j < 40; j++) {
            CHUNK_TOP(j);
            CHUNK_MMA(j);
#pragma unroll
            for (int gi = 0; gi < 2; gi++) {
                const int g = 2 * j + gi;
                const bool is5 = (g >= 72);
                const int u0 = is5 ? 2 * (g - 72) : 2 * (g - 64);
                float av[4][2][3];
#pragma unroll
                for (int r = 0; r < 4; r++) {
#pragma unroll
                    for (int us = 0; us < 2; us++) {
                        const int u = u0 + us;
                        const float xx = __half2float(x1h[mmr[r] * 50 + 3 * u + 0]);
                        const float xy = __half2float(x1h[mmr[r] * 50 + 3 * u + 1]);
                        const float xz = __half2float(x1h[mmr[r] * 50 + 3 * u + 2]);
                        if (!is5) {
                            const float kb = C1IS3 * sh0r[r];
                            av[r][us][0] = kb * xx;
                            av[r][us][1] = kb * xy;
                            av[r][us][2] = kb * xz;
                        } else {
                            av[r][us][0] = C1IS6 * (xy * sh1r[r][2] - xz * sh1r[r][1]);
                            av[r][us][1] = C1IS6 * (xz * sh1r[r][0] - xx * sh1r[r][2]);
                            av[r][us][2] = C1IS6 * (xx * sh1r[r][1] - xy * sh1r[r][0]);
                        }
                    }
                }
#pragma unroll
                for (int tt = 0; tt < 4; tt++) {
                    const int us = tt >> 1;
                    const int sl = 2 * (tt & 1);
                    const float2 bv = *(const float2*)(b2s + 32 * g + 8 * tt + q2);
#pragma unroll
                    for (int rt = 0; rt < 2; rt++)
#pragma unroll
                        for (int rr = 0; rr < 2; rr++) {
                            const int r = 2 * rt + rr;
                            float* cc = c2[rt][4 * gi + tt];
                            const float D0 = cc[2 * rr] + bv.x;
                            const float D1 = cc[2 * rr + 1] + bv.y;
#pragma unroll
                            for (int k = 0; k < 3; k++) {
                                accV[r][sl][k]     += av[r][us][k] * D0;
                                accV[r][sl + 1][k] += av[r][us][k] * D1;
                            }
                        }
                }
            }
        }
#pragma unroll
        for (int r = 0; r < 4; r++) {
            float* segp = g_seg + (size_t)srcs[mmr[r]] * NODE_DIM;
#pragma unroll
            for (int ws = 0; ws < 2; ws++)
#pragma unroll
                for (int b = 0; b < 2; b++) {
                    const int wc = 8 * ws + q2 + b;
#pragma unroll
                    for (int k = 0; k < 3; k++)
                        atomicAdd(segp + 32 + 3 * wc + k, accV[r][2 * ws + b][k]);
                }
        }
    }
}

// ---------------- node epilogue ----------------
__global__ void node_kernel(const float* __restrict__ node_attr,
                            const float* __restrict__ mean_shift,
                            const float* __restrict__ aw,
                            const float* __restrict__ ab,
                            float* __restrict__ out) {
    const int warp = (blockIdx.x * blockDim.x + threadIdx.x) >> 5;
    const int lane = threadIdx.x & 31;
    if (warp >= N_NODES) return;
    const unsigned full = 0xFFFFFFFFu;

    const float inv = 1.0f / fmaxf(g_cnt[warp], 1.0f);
    const float* seg = g_seg + (size_t)warp * NODE_DIM;
    const float* na  = node_attr + (size_t)warp * NODE_DIM;

    float o0 = seg[lane] * inv + na[lane];
    float mval = o0;
#pragma unroll
    for (int off = 16; off; off >>= 1) mval += __shfl_xor_sync(full, mval, off);
    mval *= (1.0f / 32.0f);
    const float f0 = o0 - mval * mean_shift[lane];
    float s = f0 * f0;
#pragma unroll
    for (int off = 16; off; off >>= 1) s += __shfl_xor_sync(full, s, off);
    const float sc0 = rsqrtf(s * (1.0f / 32.0f) + EPS_LN) * aw[lane];
    out[(size_t)warp * NODE_DIM + lane] = f0 * sc0 + ab[lane];

    float vx = 0.0f, vy = 0.0f, vz = 0.0f, msv = 0.0f;
    if (lane < 16) {
        vx = seg[32 + 3 * lane + 0] * inv + na[32 + 3 * lane + 0];
        vy = seg[32 + 3 * lane + 1] * inv + na[32 + 3 * lane + 1];
        vz = seg[32 + 3 * lane + 2] * inv + na[32 + 3 * lane + 2];
        msv = mean_shift[32 + lane];
    }
    float mx = vx, my = vy, mz = vz;
#pragma unroll
    for (int off = 16; off; off >>= 1) {
        mx += __shfl_xor_sync(full, mx, off);
        my += __shfl_xor_sync(full, my, off);
        mz += __shfl_xor_sync(full, mz, off);
    }
    mx *= (1.0f / 16.0f); my *= (1.0f / 16.0f); mz *= (1.0f / 16.0f);
    const float fx = vx - mx * msv;
    const float fy = vy - my * msv;
    const float fz = vz - mz * msv;
    float sq = (lane < 16) ? (fx * fx + fy * fy + fz * fz) : 0.0f;
#pragma unroll
    for (int off = 16; off; off >>= 1) sq += __shfl_xor_sync(full, sq, off);
    if (lane < 16) {
        const float sc1 = rsqrtf(sq * (1.0f / 48.0f) + EPS_LN) * aw[32 + lane];
        out[(size_t)warp * NODE_DIM + 32 + 3 * lane + 0] = fx * sc1;
        out[(size_t)warp * NODE_DIM + 32 + 3 * lane + 1] = fy * sc1;
        out[(size_t)warp * NODE_DIM + 32 + 3 * lane + 2] = fz * sc1;
    }
}

// ---------------- launch ----------------
extern "C" void kernel_launch(void* const* d_in, const int* in_sizes, int n_in,
                              void* d_out, int out_size) {
    const float* node_attr  = (const float*)d_in[0];
    const float* edge_attr  = (const float*)d_in[1];
    const float* edge_sh    = (const float*)d_in[2];
    const float* fc_w1      = (const float*)d_in[3];
    const float* fc_b1      = (const float*)d_in[4];
    const float* fc_w2      = (const float*)d_in[5];
    const float* fc_b2      = (const float*)d_in[6];
    const float* mean_shift = (const float*)d_in[7];
    const float* aw         = (const float*)d_in[8];
    const float* ab         = (const float*)d_in[9];
    const int*   edge_index = (const int*)d_in[10];
    float* out = (float*)d_out;

    cudaFuncSetAttribute(edge_kernel, cudaFuncAttributeMaxDynamicSharedMemorySize, (int)EDGE_SMEM);

    void* seg_ptr = nullptr;
    void* cnt_ptr = nullptr;
    cudaGetSymbolAddress(&seg_ptr, g_seg);
    cudaGetSymbolAddress(&cnt_ptr, g_cnt);
    cudaMemsetAsync(seg_ptr, 0, sizeof(float) * (size_t)N_NODES * NODE_DIM);
    cudaMemsetAsync(cnt_ptr, 0, sizeof(float) * N_NODES);

    prep_kernel<<<321, 256>>>(fc_w1, fc_w2);
    edge_kernel<<<NTILES, ETHREADS, EDGE_SMEM>>>(node_attr, edge_attr, edge_sh, fc_b1, fc_b2, edge_index);
    node_kernel<<<(N_NODES * 32 + 255) / 256, 256>>>(node_attr, mean_shift, aw, ab, out);
}